// round 1
// baseline (speedup 1.0000x reference)
#include <cuda_runtime.h>
#include <cstdint>

#define NUM_T 8192
#define DIM   1024
#define NEXP  8
#define DFFN  2048
#define OUT_MAT (NUM_T * DIM)

#define BM 128
#define BN 128
#define BK 32
#define SA_STRIDE 36
#define SB_STRIDE 136
#define SA_SZ (BM * SA_STRIDE)   // 4608 floats
#define SB_SZ (BK * SB_STRIDE)   // 4352 floats
#define SMEM_FLOATS (2 * (SA_SZ + SB_SZ))   // 17920 floats = 71680 B

// ---------------- scratch (device globals; no allocations allowed) ----------------
__device__ float g_Xtf[NUM_T * DIM];              //  32 MB tf32-rounded x
__device__ float g_W1tf[DIM * NEXP * DFFN];       //  64 MB tf32-rounded w1
__device__ float g_W2tf[NEXP * DFFN * DIM];       //  64 MB tf32-rounded w2
__device__ float g_H[NUM_T * 2 * DFFN];           // 128 MB intermediate (scaled, tf32)
__device__ int   g_list[NEXP * NUM_T];            // per-expert token lists
__device__ float g_wsel[NEXP * NUM_T];            // per-selection routing weight
__device__ int   g_count[NEXP];
__device__ int   g_off[NEXP];
__device__ float g_psum[NEXP];
__device__ float g_zsum;

// ---------------- small helpers ----------------
__device__ __forceinline__ float to_tf32(float x) {
    uint32_t o;
    asm volatile("cvt.rna.tf32.f32 %0, %1;" : "=r"(o) : "f"(x));
    return __uint_as_float(o);
}
__device__ __forceinline__ unsigned cvta_s(const void* p) {
    return (unsigned)__cvta_generic_to_shared((void*)p);
}
__device__ __forceinline__ void cpa16(float* sdst, const float* gsrc) {
    asm volatile("cp.async.cg.shared.global [%0], [%1], 16;"
                 :: "r"(cvta_s(sdst)), "l"(gsrc));
}
__device__ __forceinline__ void cpa_commit() {
    asm volatile("cp.async.commit_group;");
}
template<int N> __device__ __forceinline__ void cpa_wait() {
    asm volatile("cp.async.wait_group %0;" :: "n"(N));
}
__device__ __forceinline__ void ldsm4(uint32_t* a, const float* p) {
    asm volatile("ldmatrix.sync.aligned.m8n8.x4.shared.b16 {%0,%1,%2,%3}, [%4];"
                 : "=r"(a[0]), "=r"(a[1]), "=r"(a[2]), "=r"(a[3])
                 : "r"(cvta_s(p)));
}
__device__ __forceinline__ void mma8(float* c, const uint32_t* a, const uint32_t* b) {
    asm volatile("mma.sync.aligned.m16n8k8.row.col.f32.tf32.tf32.f32 "
                 "{%0,%1,%2,%3}, {%4,%5,%6,%7}, {%8,%9}, {%0,%1,%2,%3};"
                 : "+f"(c[0]), "+f"(c[1]), "+f"(c[2]), "+f"(c[3])
                 : "r"(a[0]), "r"(a[1]), "r"(a[2]), "r"(a[3]),
                   "r"(b[0]), "r"(b[1]));
}

// ---------------- kernel 0: zero the tiny accumulators ----------------
__global__ void zero_kernel() {
    int t = threadIdx.x;
    if (t < NEXP) { g_count[t] = 0; g_psum[t] = 0.f; }
    if (t == 0)   { g_zsum = 0.f; }
}

// ---------------- kernel 1: tf32-round x, w1, w2 into scratch ----------------
__global__ void convert_kernel(const float4* __restrict__ x,
                               const float4* __restrict__ w1,
                               const float4* __restrict__ w2) {
    const unsigned NX = (NUM_T * DIM) / 4;          // 2097152
    const unsigned NW = (DIM * NEXP * DFFN) / 4;    // 4194304
    unsigned i = blockIdx.x * 256u + threadIdx.x;   // total NX + 2*NW = 10485760
    float4 v; float4* dst;
    if (i < NX)            { v = x[i];            dst = (float4*)g_Xtf  + i; }
    else if (i < NX + NW)  { v = w1[i - NX];      dst = (float4*)g_W1tf + (i - NX); }
    else                   { v = w2[i - NX - NW]; dst = (float4*)g_W2tf + (i - NX - NW); }
    v.x = to_tf32(v.x); v.y = to_tf32(v.y);
    v.z = to_tf32(v.z); v.w = to_tf32(v.w);
    *dst = v;
}

// ---------------- kernel 2: router (logits, softmax, top-2, scatter lists) ----------------
__global__ void router_kernel(const float* __restrict__ x,
                              const float* __restrict__ wr) {
    __shared__ float swr[NEXP][DIM];   // transposed router weights, conflict-free reads
    __shared__ float s_p[NEXP];
    __shared__ float s_z;

    int tid = threadIdx.x;
    for (int i = tid; i < NEXP * DIM; i += 256) {
        int d = i >> 3, e = i & 7;
        swr[e][d] = wr[i];
    }
    if (tid < NEXP) s_p[tid] = 0.f;
    if (tid == 0)   s_z = 0.f;
    __syncthreads();

    int lane = tid & 31, warp = tid >> 5;
    int t = blockIdx.x * 8 + warp;          // one warp per token, 8 tokens/block

    float acc[NEXP];
#pragma unroll
    for (int e = 0; e < NEXP; e++) acc[e] = 0.f;

    const float4* xr = (const float4*)(x + (size_t)t * DIM);
    for (int c = lane; c < DIM / 4; c += 32) {
        float4 xv = xr[c];
#pragma unroll
        for (int e = 0; e < NEXP; e++) {
            float4 wv = *(const float4*)&swr[e][c * 4];
            acc[e] += xv.x * wv.x + xv.y * wv.y + xv.z * wv.z + xv.w * wv.w;
        }
    }
#pragma unroll
    for (int e = 0; e < NEXP; e++)
        for (int o = 16; o; o >>= 1) acc[e] += __shfl_xor_sync(0xffffffffu, acc[e], o);

    if (lane == 0) {
        float m = acc[0];
#pragma unroll
        for (int e = 1; e < NEXP; e++) m = fmaxf(m, acc[e]);
        float p[NEXP], se = 0.f;
#pragma unroll
        for (int e = 0; e < NEXP; e++) { p[e] = expf(acc[e] - m); se += p[e]; }
        float inv = 1.f / se;
#pragma unroll
        for (int e = 0; e < NEXP; e++) p[e] *= inv;
        float lse = m + logf(se);

        // top-2 (stable: lowest index wins ties, matching jax top_k)
        int e0 = 0;
#pragma unroll
        for (int e = 1; e < NEXP; e++) if (p[e] > p[e0]) e0 = e;
        int e1 = (e0 == 0) ? 1 : 0;
#pragma unroll
        for (int e = 0; e < NEXP; e++) if (e != e0 && p[e] > p[e1]) e1 = e;

        float w0 = p[e0], w1v = p[e1], s = w0 + w1v;
        w0 /= s; w1v /= s;

        int pos = atomicAdd(&g_count[e0], 1);
        g_list[e0 * NUM_T + pos] = t;  g_wsel[e0 * NUM_T + pos] = w0;
        pos = atomicAdd(&g_count[e1], 1);
        g_list[e1 * NUM_T + pos] = t;  g_wsel[e1 * NUM_T + pos] = w1v;

        atomicAdd(&s_z, lse * lse);
#pragma unroll
        for (int e = 0; e < NEXP; e++) atomicAdd(&s_p[e], p[e]);
    }
    __syncthreads();
    if (tid < NEXP) atomicAdd(&g_psum[tid], s_p[tid]);
    if (tid == 0)   atomicAdd(&g_zsum, s_z);
}

// ---------------- kernel 3: offsets + aux-loss outputs ----------------
__global__ void finalize_kernel(float* out_tail) {
    if (threadIdx.x == 0) {
        int o = 0;
#pragma unroll
        for (int e = 0; e < NEXP; e++) { g_off[e] = o; o += g_count[e]; }
        float z = g_zsum / (float)NUM_T;
        float lb = 0.f;
#pragma unroll
        for (int e = 0; e < NEXP; e++) {
            float f = (float)g_count[e] / (float)(NUM_T * 2);
            lb += f * (g_psum[e] / (float)NUM_T);
        }
        lb *= (float)NEXP;
        out_tail[0] = z;
        out_tail[1] = lb;
#pragma unroll
        for (int e = 0; e < NEXP; e++)
            out_tail[2 + e] = (float)g_count[e] / (float)(NUM_T * 2);
    }
}

// ---------------- grouped TF32 tensor-core GEMM ----------------
// MODE 1: H[row] = wsel * (gather(x) @ W1_e)   (tf32-rounded store)
// MODE 2: out[token] += H @ W2_e               (atomicAdd scatter)
template<int KD, int MODE>
__global__ __launch_bounds__(256) void moe_gemm(float* out) {
    const int e   = blockIdx.z;
    const int cnt = g_count[e];
    const int m0  = blockIdx.x * BM;
    if (m0 >= cnt) return;
    const int n0  = blockIdx.y * BN;
    const int off = g_off[e];

    extern __shared__ float smem[];
    float* sA = smem;
    float* sB = smem + 2 * SA_SZ;

    const int tid = threadIdx.x, lane = tid & 31, warp = tid >> 5;

    // ---- gathered A row pointers (clamped for partial tiles) ----
    const float* aptr[4];
#pragma unroll
    for (int i = 0; i < 4; i++) {
        int rr = m0 + (tid >> 3) + i * 32;
        if (rr >= cnt) rr = cnt - 1;
        if (MODE == 1) {
            int tok = g_list[e * NUM_T + rr];
            aptr[i] = g_Xtf + (size_t)tok * DIM + (tid & 7) * 4;
        } else {
            aptr[i] = g_H + (size_t)(off + rr) * DFFN + (tid & 7) * 4;
        }
    }
    const int LDB = (MODE == 1) ? (NEXP * DFFN) : DIM;
    const float* bbase = (MODE == 1)
        ? (g_W1tf + (size_t)warp * LDB + e * DFFN + n0 + lane * 4)
        : (g_W2tf + ((size_t)e * DFFN + warp) * DIM + n0 + lane * 4);

    auto load_stage = [&](int it, int s) {
        float* sAs = sA + s * SA_SZ;
        float* sBs = sB + s * SB_SZ;
        int k0 = it * BK;
#pragma unroll
        for (int i = 0; i < 4; i++)
            cpa16(sAs + ((tid >> 3) + i * 32) * SA_STRIDE + (tid & 7) * 4,
                  aptr[i] + k0);
#pragma unroll
        for (int i = 0; i < 4; i++)
            cpa16(sBs + (warp + i * 8) * SB_STRIDE + lane * 4,
                  bbase + (size_t)(k0 + i * 8) * LDB);
        cpa_commit();
    };

    float acc[2][8][4];
#pragma unroll
    for (int a = 0; a < 2; a++)
#pragma unroll
        for (int b = 0; b < 8; b++)
#pragma unroll
            for (int c = 0; c < 4; c++) acc[a][b][c] = 0.f;

    const int wm = (warp & 3) * 32;
    const int wn = (warp >> 2) * 64;

    auto compute_stage = [&](int s) {
        float* sAs = sA + s * SA_SZ;
        float* sBs = sB + s * SB_SZ;
#pragma unroll
        for (int ks = 0; ks < 4; ks++) {
            uint32_t afr[2][4];
#pragma unroll
            for (int tm = 0; tm < 2; tm++) {
                const float* p = sAs + (wm + tm * 16 + (lane & 15)) * SA_STRIDE
                               + ks * 8 + ((lane >> 4) << 2);
                ldsm4(afr[tm], p);
            }
            uint32_t bfr[8][2];
            int kb = ks * 8 + (lane & 3);
            int nb = wn + (lane >> 2);
#pragma unroll
            for (int tn = 0; tn < 8; tn++) {
                bfr[tn][0] = __float_as_uint(sBs[kb * SB_STRIDE + nb + tn * 8]);
                bfr[tn][1] = __float_as_uint(sBs[(kb + 4) * SB_STRIDE + nb + tn * 8]);
            }
#pragma unroll
            for (int tm = 0; tm < 2; tm++)
#pragma unroll
                for (int tn = 0; tn < 8; tn++)
                    mma8(acc[tm][tn], afr[tm], bfr[tn]);
        }
    };

    constexpr int ITERS = KD / BK;
    load_stage(0, 0);
    load_stage(1, 1);
    cpa_wait<1>();
    __syncthreads();
#pragma unroll 1
    for (int it = 0; it < ITERS; ++it) {
        compute_stage(it & 1);
        __syncthreads();
        if (it + 2 < ITERS) {
            load_stage(it + 2, it & 1);
            cpa_wait<1>();
            __syncthreads();
        } else if (it + 1 < ITERS) {
            cpa_wait<0>();
            __syncthreads();
        }
    }

    // ---- epilogue ----
#pragma unroll
    for (int tm = 0; tm < 2; tm++) {
#pragma unroll
        for (int half = 0; half < 2; half++) {
            int r  = wm + tm * 16 + (lane >> 2) + half * 8;
            int gr = m0 + r;
            if (gr < cnt) {
                if (MODE == 1) {
                    float w = g_wsel[e * NUM_T + gr];
                    float* hrow = g_H + (size_t)(off + gr) * DFFN + n0 + wn;
#pragma unroll
                    for (int tn = 0; tn < 8; tn++) {
                        int c = tn * 8 + (lane & 3) * 2;
                        float2 v;
                        v.x = to_tf32(acc[tm][tn][half * 2 + 0] * w);
                        v.y = to_tf32(acc[tm][tn][half * 2 + 1] * w);
                        *(float2*)(hrow + c) = v;
                    }
                } else {
                    int tok = g_list[e * NUM_T + gr];
                    float* orow = out + (size_t)tok * DIM + n0 + wn;
#pragma unroll
                    for (int tn = 0; tn < 8; tn++) {
                        int c = tn * 8 + (lane & 3) * 2;
                        atomicAdd(orow + c,     acc[tm][tn][half * 2 + 0]);
                        atomicAdd(orow + c + 1, acc[tm][tn][half * 2 + 1]);
                    }
                }
            }
        }
    }
}

// ---------------- launch ----------------
extern "C" void kernel_launch(void* const* d_in, const int* in_sizes, int n_in,
                              void* d_out, int out_size) {
    const float* x  = (const float*)d_in[0];
    const float* wr = (const float*)d_in[1];
    const float* w1 = (const float*)d_in[2];
    const float* w2 = (const float*)d_in[3];
    float* out = (float*)d_out;

    const size_t smem = (size_t)SMEM_FLOATS * sizeof(float);   // 71680 B
    cudaFuncSetAttribute(moe_gemm<DIM, 1>,
                         cudaFuncAttributeMaxDynamicSharedMemorySize, (int)smem);
    cudaFuncSetAttribute(moe_gemm<DFFN, 2>,
                         cudaFuncAttributeMaxDynamicSharedMemorySize, (int)smem);

    cudaMemsetAsync(out, 0, (size_t)OUT_MAT * sizeof(float), 0);
    zero_kernel<<<1, 32>>>();
    convert_kernel<<<40960, 256>>>((const float4*)x, (const float4*)w1,
                                   (const float4*)w2);
    router_kernel<<<NUM_T / 8, 256>>>(x, wr);
    finalize_kernel<<<1, 32>>>(out + OUT_MAT);

    // GEMM1: H = wsel * (gather(x) @ W1_e), grid covers worst-case rows per expert
    moe_gemm<DIM, 1><<<dim3(NUM_T / BM, DFFN / BN, NEXP), 256, smem>>>(nullptr);
    // GEMM2: out += H @ W2_e
    moe_gemm<DFFN, 2><<<dim3(NUM_T / BM, DIM / BN, NEXP), 256, smem>>>(out);
}

// round 2
// speedup vs baseline: 1.6547x; 1.6547x over previous
#include <cuda_runtime.h>
#include <cstdint>

#define NUM_T 8192
#define DIM   1024
#define NEXP  8
#define DFFN  2048
#define OUT_MAT (NUM_T * DIM)

#define BM 128
#define BN 128
#define BK 32
#define SA_STRIDE 36
#define SB_STRIDE 136
#define SA_SZ (BM * SA_STRIDE)   // 4608 floats
#define SB_SZ (BK * SB_STRIDE)   // 4352 floats
#define SMEM_FLOATS (2 * (SA_SZ + SB_SZ))   // 17920 floats = 71680 B

// ---------------- scratch (device globals; no allocations allowed) ----------------
__device__ float g_Xtf[NUM_T * DIM];              //  32 MB tf32-rounded x
__device__ float g_W1tf[DIM * NEXP * DFFN];       //  64 MB tf32-rounded w1
__device__ float g_W2tf[NEXP * DFFN * DIM];       //  64 MB tf32-rounded w2
__device__ float g_M[NEXP * DIM * DIM];           //  33 MB fused expert matrices
__device__ int   g_list[NEXP * NUM_T];            // per-expert token lists
__device__ float g_wsel[NEXP * NUM_T];            // per-selection routing weight
__device__ int   g_count[NEXP];
__device__ float g_psum[NEXP];
__device__ float g_zsum;

// ---------------- small helpers ----------------
__device__ __forceinline__ float to_tf32(float x) {
    uint32_t o;
    asm volatile("cvt.rna.tf32.f32 %0, %1;" : "=r"(o) : "f"(x));
    return __uint_as_float(o);
}
__device__ __forceinline__ unsigned cvta_s(const void* p) {
    return (unsigned)__cvta_generic_to_shared((void*)p);
}
__device__ __forceinline__ void cpa16(float* sdst, const float* gsrc) {
    asm volatile("cp.async.cg.shared.global [%0], [%1], 16;"
                 :: "r"(cvta_s(sdst)), "l"(gsrc));
}
__device__ __forceinline__ void cpa_commit() {
    asm volatile("cp.async.commit_group;");
}
template<int N> __device__ __forceinline__ void cpa_wait() {
    asm volatile("cp.async.wait_group %0;" :: "n"(N));
}
__device__ __forceinline__ void ldsm4(uint32_t* a, const float* p) {
    asm volatile("ldmatrix.sync.aligned.m8n8.x4.shared.b16 {%0,%1,%2,%3}, [%4];"
                 : "=r"(a[0]), "=r"(a[1]), "=r"(a[2]), "=r"(a[3])
                 : "r"(cvta_s(p)));
}
__device__ __forceinline__ void mma8(float* c, const uint32_t* a, const uint32_t* b) {
    asm volatile("mma.sync.aligned.m16n8k8.row.col.f32.tf32.tf32.f32 "
                 "{%0,%1,%2,%3}, {%4,%5,%6,%7}, {%8,%9}, {%0,%1,%2,%3};"
                 : "+f"(c[0]), "+f"(c[1]), "+f"(c[2]), "+f"(c[3])
                 : "r"(a[0]), "r"(a[1]), "r"(a[2]), "r"(a[3]),
                   "r"(b[0]), "r"(b[1]));
}
// vectorized fp32 reduction to global (FA3-style), halves REDG message count
__device__ __forceinline__ void red2(float* p, float a, float b) {
    asm volatile("red.global.v2.f32.add [%0], {%1, %2};"
                 :: "l"(p), "f"(a), "f"(b) : "memory");
}

// ---------------- kernel 0: zero the tiny accumulators ----------------
__global__ void zero_kernel() {
    int t = threadIdx.x;
    if (t < NEXP) { g_count[t] = 0; g_psum[t] = 0.f; }
    if (t == 0)   { g_zsum = 0.f; }
}

// ---------------- kernel 1: tf32-round x, w1, w2 into scratch ----------------
__global__ void convert_kernel(const float4* __restrict__ x,
                               const float4* __restrict__ w1,
                               const float4* __restrict__ w2) {
    const unsigned NX = (NUM_T * DIM) / 4;          // 2097152
    const unsigned NW = (DIM * NEXP * DFFN) / 4;    // 4194304
    unsigned i = blockIdx.x * 256u + threadIdx.x;   // total NX + 2*NW = 10485760
    float4 v; float4* dst;
    if (i < NX)            { v = x[i];            dst = (float4*)g_Xtf  + i; }
    else if (i < NX + NW)  { v = w1[i - NX];      dst = (float4*)g_W1tf + (i - NX); }
    else                   { v = w2[i - NX - NW]; dst = (float4*)g_W2tf + (i - NX - NW); }
    v.x = to_tf32(v.x); v.y = to_tf32(v.y);
    v.z = to_tf32(v.z); v.w = to_tf32(v.w);
    *dst = v;
}

// ---------------- kernel 2: router (logits, softmax, top-2, scatter lists) ----------------
__global__ void router_kernel(const float* __restrict__ x,
                              const float* __restrict__ wr) {
    __shared__ float swr[NEXP][DIM];   // transposed router weights, conflict-free reads
    __shared__ float s_p[NEXP];
    __shared__ float s_z;

    int tid = threadIdx.x;
    for (int i = tid; i < NEXP * DIM; i += 256) {
        int d = i >> 3, e = i & 7;
        swr[e][d] = wr[i];
    }
    if (tid < NEXP) s_p[tid] = 0.f;
    if (tid == 0)   s_z = 0.f;
    __syncthreads();

    int lane = tid & 31, warp = tid >> 5;
    int t = blockIdx.x * 8 + warp;          // one warp per token, 8 tokens/block

    float acc[NEXP];
#pragma unroll
    for (int e = 0; e < NEXP; e++) acc[e] = 0.f;

    const float4* xr = (const float4*)(x + (size_t)t * DIM);
    for (int c = lane; c < DIM / 4; c += 32) {
        float4 xv = xr[c];
#pragma unroll
        for (int e = 0; e < NEXP; e++) {
            float4 wv = *(const float4*)&swr[e][c * 4];
            acc[e] += xv.x * wv.x + xv.y * wv.y + xv.z * wv.z + xv.w * wv.w;
        }
    }
#pragma unroll
    for (int e = 0; e < NEXP; e++)
        for (int o = 16; o; o >>= 1) acc[e] += __shfl_xor_sync(0xffffffffu, acc[e], o);

    if (lane == 0) {
        float m = acc[0];
#pragma unroll
        for (int e = 1; e < NEXP; e++) m = fmaxf(m, acc[e]);
        float p[NEXP], se = 0.f;
#pragma unroll
        for (int e = 0; e < NEXP; e++) { p[e] = expf(acc[e] - m); se += p[e]; }
        float inv = 1.f / se;
#pragma unroll
        for (int e = 0; e < NEXP; e++) p[e] *= inv;
        float lse = m + logf(se);

        // top-2 (stable: lowest index wins ties, matching jax top_k)
        int e0 = 0;
#pragma unroll
        for (int e = 1; e < NEXP; e++) if (p[e] > p[e0]) e0 = e;
        int e1 = (e0 == 0) ? 1 : 0;
#pragma unroll
        for (int e = 0; e < NEXP; e++) if (e != e0 && p[e] > p[e1]) e1 = e;

        float w0 = p[e0], w1v = p[e1], s = w0 + w1v;
        w0 /= s; w1v /= s;

        int pos = atomicAdd(&g_count[e0], 1);
        g_list[e0 * NUM_T + pos] = t;  g_wsel[e0 * NUM_T + pos] = w0;
        pos = atomicAdd(&g_count[e1], 1);
        g_list[e1 * NUM_T + pos] = t;  g_wsel[e1 * NUM_T + pos] = w1v;

        atomicAdd(&s_z, lse * lse);
#pragma unroll
        for (int e = 0; e < NEXP; e++) atomicAdd(&s_p[e], p[e]);
    }
    __syncthreads();
    if (tid < NEXP) atomicAdd(&g_psum[tid], s_p[tid]);
    if (tid == 0)   atomicAdd(&g_zsum, s_z);
}

// ---------------- kernel 3: aux-loss outputs ----------------
__global__ void finalize_kernel(float* out_tail) {
    if (threadIdx.x == 0) {
        float z = g_zsum / (float)NUM_T;
        float lb = 0.f;
#pragma unroll
        for (int e = 0; e < NEXP; e++) {
            float f = (float)g_count[e] / (float)(NUM_T * 2);
            lb += f * (g_psum[e] / (float)NUM_T);
        }
        lb *= (float)NEXP;
        out_tail[0] = z;
        out_tail[1] = lb;
#pragma unroll
        for (int e = 0; e < NEXP; e++)
            out_tail[2 + e] = (float)g_count[e] / (float)(NUM_T * 2);
    }
}

// ---------------- TF32 tensor-core GEMM ----------------
// MODE 3: M_e = W1_e @ W2_e            (dense, tf32-rounded store to g_M)
// MODE 4: out[tok] += wsel * (gather(x) @ M_e)   (vector-red scatter)
template<int KD, int MODE>
__global__ __launch_bounds__(256) void moe_gemm(float* out) {
    const int e   = blockIdx.z;
    const int cnt = (MODE == 3) ? DIM : g_count[e];
    const int m0  = blockIdx.x * BM;
    if (m0 >= cnt) return;
    const int n0  = blockIdx.y * BN;

    extern __shared__ float smem[];
    float* sA = smem;
    float* sB = smem + 2 * SA_SZ;

    const int tid = threadIdx.x, lane = tid & 31, warp = tid >> 5;

    // ---- A row pointers (gathered for MODE 4; clamped for partial tiles) ----
    const float* aptr[4];
#pragma unroll
    for (int i = 0; i < 4; i++) {
        int rr = m0 + (tid >> 3) + i * 32;
        if (MODE == 3) {
            aptr[i] = g_W1tf + (size_t)rr * (NEXP * DFFN) + (size_t)e * DFFN
                    + (tid & 7) * 4;
        } else {
            if (rr >= cnt) rr = cnt - 1;
            int tok = g_list[e * NUM_T + rr];
            aptr[i] = g_Xtf + (size_t)tok * DIM + (tid & 7) * 4;
        }
    }
    const int LDB = DIM;
    const float* bbase = (MODE == 3)
        ? (g_W2tf + ((size_t)e * DFFN + warp) * DIM + n0 + lane * 4)
        : (g_M + (size_t)e * DIM * DIM + (size_t)warp * DIM + n0 + lane * 4);

    auto load_stage = [&](int it, int s) {
        float* sAs = sA + s * SA_SZ;
        float* sBs = sB + s * SB_SZ;
        int k0 = it * BK;
#pragma unroll
        for (int i = 0; i < 4; i++)
            cpa16(sAs + ((tid >> 3) + i * 32) * SA_STRIDE + (tid & 7) * 4,
                  aptr[i] + k0);
#pragma unroll
        for (int i = 0; i < 4; i++)
            cpa16(sBs + (warp + i * 8) * SB_STRIDE + lane * 4,
                  bbase + (size_t)(k0 + i * 8) * LDB);
        cpa_commit();
    };

    float acc[2][8][4];
#pragma unroll
    for (int a = 0; a < 2; a++)
#pragma unroll
        for (int b = 0; b < 8; b++)
#pragma unroll
            for (int c = 0; c < 4; c++) acc[a][b][c] = 0.f;

    const int wm = (warp & 3) * 32;
    const int wn = (warp >> 2) * 64;

    auto compute_stage = [&](int s) {
        float* sAs = sA + s * SA_SZ;
        float* sBs = sB + s * SB_SZ;
#pragma unroll
        for (int ks = 0; ks < 4; ks++) {
            uint32_t afr[2][4];
#pragma unroll
            for (int tm = 0; tm < 2; tm++) {
                const float* p = sAs + (wm + tm * 16 + (lane & 15)) * SA_STRIDE
                               + ks * 8 + ((lane >> 4) << 2);
                ldsm4(afr[tm], p);
            }
            uint32_t bfr[8][2];
            int kb = ks * 8 + (lane & 3);
            int nb = wn + (lane >> 2);
#pragma unroll
            for (int tn = 0; tn < 8; tn++) {
                bfr[tn][0] = __float_as_uint(sBs[kb * SB_STRIDE + nb + tn * 8]);
                bfr[tn][1] = __float_as_uint(sBs[(kb + 4) * SB_STRIDE + nb + tn * 8]);
            }
#pragma unroll
            for (int tm = 0; tm < 2; tm++)
#pragma unroll
                for (int tn = 0; tn < 8; tn++)
                    mma8(acc[tm][tn], afr[tm], bfr[tn]);
        }
    };

    constexpr int ITERS = KD / BK;
    load_stage(0, 0);
    load_stage(1, 1);
    cpa_wait<1>();
    __syncthreads();
#pragma unroll 1
    for (int it = 0; it < ITERS; ++it) {
        compute_stage(it & 1);
        __syncthreads();
        if (it + 2 < ITERS) {
            load_stage(it + 2, it & 1);
            cpa_wait<1>();
            __syncthreads();
        } else if (it + 1 < ITERS) {
            cpa_wait<0>();
            __syncthreads();
        }
    }

    // ---- epilogue ----
#pragma unroll
    for (int tm = 0; tm < 2; tm++) {
#pragma unroll
        for (int half = 0; half < 2; half++) {
            int r  = wm + tm * 16 + (lane >> 2) + half * 8;
            int gr = m0 + r;
            if (gr < cnt) {
                if (MODE == 3) {
                    float* mrow = g_M + (size_t)e * DIM * DIM
                                + (size_t)gr * DIM + n0 + wn;
#pragma unroll
                    for (int tn = 0; tn < 8; tn++) {
                        int c = tn * 8 + (lane & 3) * 2;
                        float2 v;
                        v.x = to_tf32(acc[tm][tn][half * 2 + 0]);
                        v.y = to_tf32(acc[tm][tn][half * 2 + 1]);
                        *(float2*)(mrow + c) = v;
                    }
                } else {
                    float w   = g_wsel[e * NUM_T + gr];
                    int   tok = g_list[e * NUM_T + gr];
                    float* orow = out + (size_t)tok * DIM + n0 + wn;
#pragma unroll
                    for (int tn = 0; tn < 8; tn++) {
                        int c = tn * 8 + (lane & 3) * 2;
                        red2(orow + c,
                             w * acc[tm][tn][half * 2 + 0],
                             w * acc[tm][tn][half * 2 + 1]);
                    }
                }
            }
        }
    }
}

// ---------------- launch ----------------
extern "C" void kernel_launch(void* const* d_in, const int* in_sizes, int n_in,
                              void* d_out, int out_size) {
    const float* x  = (const float*)d_in[0];
    const float* wr = (const float*)d_in[1];
    const float* w1 = (const float*)d_in[2];
    const float* w2 = (const float*)d_in[3];
    float* out = (float*)d_out;

    const size_t smem = (size_t)SMEM_FLOATS * sizeof(float);   // 71680 B
    cudaFuncSetAttribute(moe_gemm<DFFN, 3>,
                         cudaFuncAttributeMaxDynamicSharedMemorySize, (int)smem);
    cudaFuncSetAttribute(moe_gemm<DIM, 4>,
                         cudaFuncAttributeMaxDynamicSharedMemorySize, (int)smem);

    cudaMemsetAsync(out, 0, (size_t)OUT_MAT * sizeof(float), 0);
    zero_kernel<<<1, 32>>>();
    convert_kernel<<<40960, 256>>>((const float4*)x, (const float4*)w1,
                                   (const float4*)w2);
    router_kernel<<<NUM_T / 8, 256>>>(x, wr);
    finalize_kernel<<<1, 32>>>(out + OUT_MAT);

    // fused expert matrices: M_e = W1_e @ W2_e   (34.4 GFLOP, dense)
    moe_gemm<DFFN, 3><<<dim3(DIM / BM, DIM / BN, NEXP), 256, smem>>>(nullptr);
    // token GEMM: out[tok] += wsel * (gather(x) @ M_e)   (34.4 GFLOP, grouped)
    moe_gemm<DIM, 4><<<dim3(NUM_T / BM, DIM / BN, NEXP), 256, smem>>>(out);
}

// round 5
// speedup vs baseline: 1.7174x; 1.0379x over previous
#include <cuda_runtime.h>
#include <cstdint>

#define NUM_T 8192
#define DIM   1024
#define NEXP  8
#define DFFN  2048
#define OUT_MAT (NUM_T * DIM)

#define BM 128
#define BN 128
#define BK 32
#define SA_STRIDE 36
#define SA_SZ (BM * SA_STRIDE)        // 4608 floats
#define SB_SZ (BK * BN)               // 4096 floats (fragment-order tile)
#define SMEM_FLOATS (2 * (SA_SZ + SB_SZ))   // 17408 floats = 69632 B

// ---------------- scratch (device globals; no allocations allowed) ----------------
__device__ float g_Xtf[NUM_T * DIM];              //  32 MB tf32-rounded x (row-major)
__device__ float g_W1tf[DIM * NEXP * DFFN];       //  64 MB tf32-rounded w1 (row-major, GEMM1 A)
__device__ float g_W2B[NEXP * 8 * 64 * 4096];     //  64 MB w2 fragment tiles (GEMM1 B)
__device__ float g_M[NEXP * DIM * DIM];           //  32 MB fused expert matrices (row-major)
__device__ float g_MB[NEXP * 8 * 32 * 4096];      //  32 MB M fragment tiles (GEMM2 B)
__device__ int   g_list[NEXP * NUM_T];
__device__ float g_wsel[NEXP * NUM_T];
__device__ int   g_count[NEXP];
__device__ float g_psum[NEXP];
__device__ float g_zsum;

// ---------------- small helpers ----------------
__device__ __forceinline__ float to_tf32(float x) {
    uint32_t o;
    asm volatile("cvt.rna.tf32.f32 %0, %1;" : "=r"(o) : "f"(x));
    return __uint_as_float(o);
}
__device__ __forceinline__ unsigned cvta_s(const void* p) {
    return (unsigned)__cvta_generic_to_shared((void*)p);
}
__device__ __forceinline__ void cpa16(float* sdst, const float* gsrc) {
    asm volatile("cp.async.cg.shared.global [%0], [%1], 16;"
                 :: "r"(cvta_s(sdst)), "l"(gsrc));
}
__device__ __forceinline__ void cpa_commit() {
    asm volatile("cp.async.commit_group;");
}
template<int N> __device__ __forceinline__ void cpa_wait() {
    asm volatile("cp.async.wait_group %0;" :: "n"(N));
}
__device__ __forceinline__ void ldsm4(uint32_t* a, const float* p) {
    asm volatile("ldmatrix.sync.aligned.m8n8.x4.shared.b16 {%0,%1,%2,%3}, [%4];"
                 : "=r"(a[0]), "=r"(a[1]), "=r"(a[2]), "=r"(a[3])
                 : "r"(cvta_s(p)));
}
__device__ __forceinline__ void mma8(float* c, const uint32_t* a, const uint32_t* b) {
    asm volatile("mma.sync.aligned.m16n8k8.row.col.f32.tf32.tf32.f32 "
                 "{%0,%1,%2,%3}, {%4,%5,%6,%7}, {%8,%9}, {%0,%1,%2,%3};"
                 : "+f"(c[0]), "+f"(c[1]), "+f"(c[2]), "+f"(c[3])
                 : "r"(a[0]), "r"(a[1]), "r"(a[2]), "r"(a[3]),
                   "r"(b[0]), "r"(b[1]));
}
__device__ __forceinline__ void red2(float* p, float a, float b) {
    asm volatile("red.global.v2.f32.add [%0], {%1, %2};"
                 :: "l"(p), "f"(a), "f"(b) : "memory");
}

// ---------------- kernel 0: zero the tiny accumulators ----------------
__global__ void zero_kernel() {
    int t = threadIdx.x;
    if (t < NEXP) { g_count[t] = 0; g_psum[t] = 0.f; }
    if (t == 0)   { g_zsum = 0.f; }
}

// ---------------- kernel 1: tf32-round x and w1 into scratch (row-major) ----------------
__global__ void convert_kernel(const float4* __restrict__ x,
                               const float4* __restrict__ w1) {
    const unsigned NX = (NUM_T * DIM) / 4;          // 2097152
    unsigned i = blockIdx.x * 256u + threadIdx.x;   // total NX + NW1 = 6291456
    float4 v; float4* dst;
    if (i < NX) { v = x[i];       dst = (float4*)g_Xtf  + i; }
    else        { v = w1[i - NX]; dst = (float4*)g_W1tf + (i - NX); }
    v.x = to_tf32(v.x); v.y = to_tf32(v.y);
    v.z = to_tf32(v.z); v.w = to_tf32(v.w);
    *dst = v;
}

// ---------------- fragment packer: B[k][n] (row-major KD x DIM per expert) -> frag tiles ----
// WHICH=0: src = w2 (kernel arg), dst = g_W2B, RND applies tf32 rounding
// WHICH=1: src = g_M (device global), dst = g_MB (already rounded)
// tile id b = (e*8 + nt)*(KD/32) + kt; tile layout [ks(4)][op(8)][lane(32)][4 floats]
// float4 = { B[k][n], B[k+4][n], B[k][n+8], B[k+4][n+8] },
//   k = kt*32 + ks*8 + (lane&3), n = nt*128 + op*16 + (lane>>2)
template<int KD, bool RND, int WHICH>
__global__ void frag_pack(const float* __restrict__ xsrc) {
    constexpr int KT = KD / 32;
    const float* src = (WHICH == 0) ? xsrc : (const float*)g_M;
    float* dst       = (WHICH == 0) ? g_W2B : g_MB;
    int b  = blockIdx.x;
    int kt = b % KT;
    int nt = (b / KT) & 7;
    int e  = b / (KT * 8);
    int t = threadIdx.x, lane = t & 31, q = t >> 5;
    const float* se = src + (size_t)e * KD * DIM;
    float* tile = dst + (size_t)b * 4096;
#pragma unroll
    for (int oi = 0; oi < 2; oi++) {
        int op = q + oi * 4;
#pragma unroll
        for (int ks = 0; ks < 4; ks++) {
            int k = kt * 32 + ks * 8 + (lane & 3);
            int n = nt * 128 + op * 16 + (lane >> 2);
            float4 v;
            v.x = se[(size_t)k * DIM + n];
            v.y = se[(size_t)(k + 4) * DIM + n];
            v.z = se[(size_t)k * DIM + n + 8];
            v.w = se[(size_t)(k + 4) * DIM + n + 8];
            if (RND) {
                v.x = to_tf32(v.x); v.y = to_tf32(v.y);
                v.z = to_tf32(v.z); v.w = to_tf32(v.w);
            }
            *(float4*)(tile + ks * 1024 + op * 128 + lane * 4) = v;
        }
    }
}

// ---------------- router (logits, softmax, top-2, scatter lists) ----------------
__global__ void router_kernel(const float* __restrict__ x,
                              const float* __restrict__ wr) {
    __shared__ float swr[NEXP][DIM];
    __shared__ float s_p[NEXP];
    __shared__ float s_z;

    int tid = threadIdx.x;
    for (int i = tid; i < NEXP * DIM; i += 256) {
        int d = i >> 3, e = i & 7;
        swr[e][d] = wr[i];
    }
    if (tid < NEXP) s_p[tid] = 0.f;
    if (tid == 0)   s_z = 0.f;
    __syncthreads();

    int lane = tid & 31, warp = tid >> 5;
    int t = blockIdx.x * 8 + warp;

    float acc[NEXP];
#pragma unroll
    for (int e = 0; e < NEXP; e++) acc[e] = 0.f;

    const float4* xr = (const float4*)(x + (size_t)t * DIM);
    for (int c = lane; c < DIM / 4; c += 32) {
        float4 xv = xr[c];
#pragma unroll
        for (int e = 0; e < NEXP; e++) {
            float4 wv = *(const float4*)&swr[e][c * 4];
            acc[e] += xv.x * wv.x + xv.y * wv.y + xv.z * wv.z + xv.w * wv.w;
        }
    }
#pragma unroll
    for (int e = 0; e < NEXP; e++)
        for (int o = 16; o; o >>= 1) acc[e] += __shfl_xor_sync(0xffffffffu, acc[e], o);

    if (lane == 0) {
        float m = acc[0];
#pragma unroll
        for (int e = 1; e < NEXP; e++) m = fmaxf(m, acc[e]);
        float p[NEXP], se = 0.f;
#pragma unroll
        for (int e = 0; e < NEXP; e++) { p[e] = expf(acc[e] - m); se += p[e]; }
        float inv = 1.f / se;
#pragma unroll
        for (int e = 0; e < NEXP; e++) p[e] *= inv;
        float lse = m + logf(se);

        int e0 = 0;
#pragma unroll
        for (int e = 1; e < NEXP; e++) if (p[e] > p[e0]) e0 = e;
        int e1 = (e0 == 0) ? 1 : 0;
#pragma unroll
        for (int e = 0; e < NEXP; e++) if (e != e0 && p[e] > p[e1]) e1 = e;

        float w0 = p[e0], w1v = p[e1], s = w0 + w1v;
        w0 /= s; w1v /= s;

        int pos = atomicAdd(&g_count[e0], 1);
        g_list[e0 * NUM_T + pos] = t;  g_wsel[e0 * NUM_T + pos] = w0;
        pos = atomicAdd(&g_count[e1], 1);
        g_list[e1 * NUM_T + pos] = t;  g_wsel[e1 * NUM_T + pos] = w1v;

        atomicAdd(&s_z, lse * lse);
#pragma unroll
        for (int e = 0; e < NEXP; e++) atomicAdd(&s_p[e], p[e]);
    }
    __syncthreads();
    if (tid < NEXP) atomicAdd(&g_psum[tid], s_p[tid]);
    if (tid == 0)   atomicAdd(&g_zsum, s_z);
}

// ---------------- aux-loss outputs ----------------
__global__ void finalize_kernel(float* out_tail) {
    if (threadIdx.x == 0) {
        float z = g_zsum / (float)NUM_T;
        float lb = 0.f;
#pragma unroll
        for (int e = 0; e < NEXP; e++) {
            float f = (float)g_count[e] / (float)(NUM_T * 2);
            lb += f * (g_psum[e] / (float)NUM_T);
        }
        lb *= (float)NEXP;
        out_tail[0] = z;
        out_tail[1] = lb;
#pragma unroll
        for (int e = 0; e < NEXP; e++)
            out_tail[2 + e] = (float)g_count[e] / (float)(NUM_T * 2);
    }
}

// ---------------- TF32 tensor-core GEMM with fragment-order B ----------------
// MODE 3: M_e = W1_e @ W2_e            (dense, tf32-rounded store to g_M)
// MODE 4: out[tok] += wsel * (gather(x) @ M_e)   (vector-red scatter)
template<int KD, int MODE>
__global__ __launch_bounds__(256) void moe_gemm(float* out) {
    constexpr int ITERS = KD / BK;
    const int e   = blockIdx.z;
    const int cnt = (MODE == 3) ? DIM : g_count[e];
    const int m0  = blockIdx.x * BM;
    if (m0 >= cnt) return;
    const int n0  = blockIdx.y * BN;

    extern __shared__ float smem[];
    float* sA = smem;
    float* sB = smem + 2 * SA_SZ;

    const int tid = threadIdx.x, lane = tid & 31, warp = tid >> 5;

    // ---- A row pointers (gathered for MODE 4; clamped for partial tiles) ----
    const float* aptr[4];
#pragma unroll
    for (int i = 0; i < 4; i++) {
        int rr = m0 + (tid >> 3) + i * 32;
        if (MODE == 3) {
            aptr[i] = g_W1tf + (size_t)rr * (NEXP * DFFN) + (size_t)e * DFFN
                    + (tid & 7) * 4;
        } else {
            if (rr >= cnt) rr = cnt - 1;
            int tok = g_list[e * NUM_T + rr];
            aptr[i] = g_Xtf + (size_t)tok * DIM + (tid & 7) * 4;
        }
    }
    // ---- B fragment tile base (contiguous 16KB tiles per BK step) ----
    const float* Bt = (MODE == 3)
        ? (g_W2B + (size_t)((e * 8 + blockIdx.y) * ITERS) * 4096)
        : (g_MB  + (size_t)((e * 8 + blockIdx.y) * ITERS) * 4096);

    auto load_stage = [&](int it, int s) {
        float* sAs = sA + s * SA_SZ;
        float* sBs = sB + s * SB_SZ;
        int k0 = it * BK;
#pragma unroll
        for (int i = 0; i < 4; i++)
            cpa16(sAs + ((tid >> 3) + i * 32) * SA_STRIDE + (tid & 7) * 4,
                  aptr[i] + k0);
        const float* bsrc = Bt + (size_t)it * 4096;
#pragma unroll
        for (int p = 0; p < 4; p++)
            cpa16(sBs + p * 1024 + tid * 4, bsrc + p * 1024 + tid * 4);
        cpa_commit();
    };

    float acc[2][8][4];
#pragma unroll
    for (int a = 0; a < 2; a++)
#pragma unroll
        for (int b = 0; b < 8; b++)
#pragma unroll
            for (int c = 0; c < 4; c++) acc[a][b][c] = 0.f;

    const int wm = (warp & 3) * 32;
    const int wng = (warp >> 2);          // n-group 0/1 -> n offset wng*64

    auto compute_stage = [&](int s) {
        float* sAs = sA + s * SA_SZ;
        float* sBs = sB + s * SB_SZ;
#pragma unroll
        for (int ks = 0; ks < 4; ks++) {
            uint32_t afr[2][4];
#pragma unroll
            for (int tm = 0; tm < 2; tm++) {
                const float* p = sAs + (wm + tm * 16 + (lane & 15)) * SA_STRIDE
                               + ks * 8 + ((lane >> 4) << 2);
                ldsm4(afr[tm], p);
            }
            uint32_t bfr[4][4];
            const float* bq = sBs + ks * 1024 + (wng * 4) * 128 + lane * 4;
#pragma unroll
            for (int t2 = 0; t2 < 4; t2++) {
                float4 v = *(const float4*)(bq + t2 * 128);
                bfr[t2][0] = __float_as_uint(v.x);
                bfr[t2][1] = __float_as_uint(v.y);
                bfr[t2][2] = __float_as_uint(v.z);
                bfr[t2][3] = __float_as_uint(v.w);
            }
#pragma unroll
            for (int tm = 0; tm < 2; tm++)
#pragma unroll
                for (int tn = 0; tn < 8; tn++)
                    mma8(acc[tm][tn], afr[tm], &bfr[tn >> 1][(tn & 1) * 2]);
        }
    };

    load_stage(0, 0);
    load_stage(1, 1);
    cpa_wait<1>();
    __syncthreads();
#pragma unroll 1
    for (int it = 0; it < ITERS; ++it) {
        compute_stage(it & 1);
        __syncthreads();
        if (it + 2 < ITERS) {
            load_stage(it + 2, it & 1);
            cpa_wait<1>();
            __syncthreads();
        } else if (it + 1 < ITERS) {
            cpa_wait<0>();
            __syncthreads();
        }
    }

    // ---- epilogue ----
#pragma unroll
    for (int tm = 0; tm < 2; tm++) {
#pragma unroll
        for (int half = 0; half < 2; half++) {
            int r  = wm + tm * 16 + (lane >> 2) + half * 8;
            int gr = m0 + r;
            if (gr < cnt) {
                if (MODE == 3) {
                    float* mrow = g_M + (size_t)e * DIM * DIM
                                + (size_t)gr * DIM + n0 + wng * 64;
#pragma unroll
                    for (int tn = 0; tn < 8; tn++) {
                        int c = tn * 8 + (lane & 3) * 2;
                        float2 v;
                        v.x = to_tf32(acc[tm][tn][half * 2 + 0]);
                        v.y = to_tf32(acc[tm][tn][half * 2 + 1]);
                        *(float2*)(mrow + c) = v;
                    }
                } else {
                    float w   = g_wsel[e * NUM_T + gr];
                    int   tok = g_list[e * NUM_T + gr];
                    float* orow = out + (size_t)tok * DIM + n0 + wng * 64;
#pragma unroll
                    for (int tn = 0; tn < 8; tn++) {
                        int c = tn * 8 + (lane & 3) * 2;
                        red2(orow + c,
                             w * acc[tm][tn][half * 2 + 0],
                             w * acc[tm][tn][half * 2 + 1]);
                    }
                }
            }
        }
    }
}

// ---------------- launch ----------------
extern "C" void kernel_launch(void* const* d_in, const int* in_sizes, int n_in,
                              void* d_out, int out_size) {
    const float* x  = (const float*)d_in[0];
    const float* wr = (const float*)d_in[1];
    const float* w1 = (const float*)d_in[2];
    const float* w2 = (const float*)d_in[3];
    float* out = (float*)d_out;

    const size_t smem = (size_t)SMEM_FLOATS * sizeof(float);   // 69632 B
    cudaFuncSetAttribute(moe_gemm<DFFN, 3>,
                         cudaFuncAttributeMaxDynamicSharedMemorySize, (int)smem);
    cudaFuncSetAttribute(moe_gemm<DIM, 4>,
                         cudaFuncAttributeMaxDynamicSharedMemorySize, (int)smem);

    cudaMemsetAsync(out, 0, (size_t)OUT_MAT * sizeof(float), 0);
    zero_kernel<<<1, 32>>>();
    convert_kernel<<<24576, 256>>>((const float4*)x, (const float4*)w1);
    frag_pack<DFFN, true, 0><<<4096, 128>>>(w2);    // w2 -> GEMM1 B tiles (g_W2B)
    router_kernel<<<NUM_T / 8, 256>>>(x, wr);
    finalize_kernel<<<1, 32>>>(out + OUT_MAT);

    // GEMM1: M_e = W1_e @ W2_e   (M=1024, N=1024, K=2048 per expert)
    moe_gemm<DFFN, 3><<<dim3(DIM / BM, DIM / BN, NEXP), 256, smem>>>(nullptr);
    // repack M (already tf32-rounded) into GEMM2 B tiles (g_M -> g_MB)
    frag_pack<DIM, false, 1><<<2048, 128>>>(nullptr);
    // GEMM2: out[tok] += wsel * (x_gathered @ M_e)   (N=1024, K=1024)
    moe_gemm<DIM, 4><<<dim3(NUM_T / BM, DIM / BN, NEXP), 256, smem>>>(out);
}

// round 6
// speedup vs baseline: 2.7468x; 1.5994x over previous
#include <cuda_runtime.h>
#include <cuda_fp16.h>
#include <cstdint>

#define NUM_T 8192
#define DIM   1024
#define NEXP  8
#define DFFN  2048
#define OUT_MAT (NUM_T * DIM)

#define BM 128
#define BN 128
#define BKH 64                          // K elements (halfs) per stage
#define SA_STRIDE 72                    // halfs, conflict-free ldmatrix
#define SA_SZ (BM * SA_STRIDE)          // 9216 halfs = 18 KB
#define SB_SZ 8192                      // halfs = 16 KB (frag tile)
#define SMEM_BYTES (2 * (SA_SZ + SB_SZ) * 2)   // 69632 B

// ---------------- scratch (device globals; no allocations allowed) ----------------
__device__ __half g_Xh [NUM_T * DIM];             // 16 MB fp16 x (row-major)
__device__ __half g_W1h[DIM * NEXP * DFFN];       // 32 MB fp16 w1 (row-major)
__device__ __half g_W2B[NEXP * 8 * 32 * 8192];    // 32 MB w2 fragment tiles (GEMM1 B)
__device__ __half g_Mh [NEXP * DIM * DIM];        // 16 MB fused expert matrices
__device__ __half g_MB [NEXP * 8 * 16 * 8192];    // 16 MB M fragment tiles (GEMM2 B)
__device__ int    g_list[NEXP * NUM_T];
__device__ float  g_wsel[NEXP * NUM_T];
__device__ int    g_count[NEXP];
__device__ float  g_psum[NEXP];
__device__ float  g_zsum;

// ---------------- small helpers ----------------
__device__ __forceinline__ unsigned cvta_s(const void* p) {
    return (unsigned)__cvta_generic_to_shared((void*)p);
}
__device__ __forceinline__ void cpa16(void* sdst, const void* gsrc) {
    asm volatile("cp.async.cg.shared.global [%0], [%1], 16;"
                 :: "r"(cvta_s(sdst)), "l"(gsrc));
}
__device__ __forceinline__ void cpa_commit() {
    asm volatile("cp.async.commit_group;");
}
template<int N> __device__ __forceinline__ void cpa_wait() {
    asm volatile("cp.async.wait_group %0;" :: "n"(N));
}
__device__ __forceinline__ void ldsm4(uint32_t* a, const void* p) {
    asm volatile("ldmatrix.sync.aligned.m8n8.x4.shared.b16 {%0,%1,%2,%3}, [%4];"
                 : "=r"(a[0]), "=r"(a[1]), "=r"(a[2]), "=r"(a[3])
                 : "r"(cvta_s(p)));
}
__device__ __forceinline__ void mma16(float* c, const uint32_t* a, const uint32_t* b) {
    asm volatile("mma.sync.aligned.m16n8k16.row.col.f32.f16.f16.f32 "
                 "{%0,%1,%2,%3}, {%4,%5,%6,%7}, {%8,%9}, {%0,%1,%2,%3};"
                 : "+f"(c[0]), "+f"(c[1]), "+f"(c[2]), "+f"(c[3])
                 : "r"(a[0]), "r"(a[1]), "r"(a[2]), "r"(a[3]),
                   "r"(b[0]), "r"(b[1]));
}
__device__ __forceinline__ void red2(float* p, float a, float b) {
    asm volatile("red.global.v2.f32.add [%0], {%1, %2};"
                 :: "l"(p), "f"(a), "f"(b) : "memory");
}

// ---------------- kernel 0: zero the tiny accumulators ----------------
__global__ void zero_kernel() {
    int t = threadIdx.x;
    if (t < NEXP) { g_count[t] = 0; g_psum[t] = 0.f; }
    if (t == 0)   { g_zsum = 0.f; }
}

// ---------------- kernel 1: fp16-round x and w1 into scratch (row-major) ----------------
__global__ void convert_kernel(const float4* __restrict__ x,
                               const float4* __restrict__ w1) {
    const unsigned NX = (NUM_T * DIM) / 4;          // 2097152
    unsigned i = blockIdx.x * 256u + threadIdx.x;   // total NX + NW1 = 6291456
    float4 v; __half* dst;
    if (i < NX) { v = x[i];       dst = g_Xh  + (size_t)i * 4; }
    else        { v = w1[i - NX]; dst = g_W1h + (size_t)(i - NX) * 4; }
    __half2 h0 = __floats2half2_rn(v.x, v.y);
    __half2 h1 = __floats2half2_rn(v.z, v.w);
    uint2 o;
    o.x = *(uint32_t*)&h0;
    o.y = *(uint32_t*)&h1;
    *(uint2*)dst = o;
}

// ---------------- fragment packer: B[k][n] -> m16n8k16 B-frag tiles (fp16) ----------
// WHICH=0: src = w2 (fp32 kernel arg) -> g_W2B ; WHICH=1: src = g_Mh (fp16) -> g_MB
// tile b = (e*8 + nt)*KT + kt covers k in [kt*64, kt*64+64), n in [nt*128, nt*128+128)
// layout: [ks(4)][tp(8)][lane(32)][8 halfs] ; per lane, per tp: two n8-tile frags
//   frag(tn) = {B[kb][n], B[kb+1][n], B[kb+8][n], B[kb+9][n]},
//   kb = kt*64 + ks*16 + 2*(lane&3), n = nt*128 + tp*16 + (tn&1)*8 + (lane>>2)
template<int KD, int WHICH>
__global__ void frag_pack(const float* __restrict__ w2src) {
    constexpr int KT = KD / 64;
    int b  = blockIdx.x;
    int kt = b % KT;
    int nt = (b / KT) & 7;
    int e  = b / (KT * 8);
    int t = threadIdx.x, lane = t & 31, slot = t >> 5;
    __half* tile = ((WHICH == 0) ? g_W2B : g_MB) + (size_t)b * 8192;
#pragma unroll
    for (int j = 0; j < 4; j++) {
        int idx = slot * 4 + j;           // 0..31 -> (ks, tp)
        int ks = idx >> 3, tp = idx & 7;
        int kb = kt * 64 + ks * 16 + 2 * (lane & 3);
        int n  = nt * 128 + tp * 16 + (lane >> 2);
        __half h[8];
        if (WHICH == 0) {
            const float* se = w2src + (size_t)e * KD * DIM;
            h[0] = __float2half_rn(se[(size_t)kb * DIM + n]);
            h[1] = __float2half_rn(se[(size_t)(kb + 1) * DIM + n]);
            h[2] = __float2half_rn(se[(size_t)(kb + 8) * DIM + n]);
            h[3] = __float2half_rn(se[(size_t)(kb + 9) * DIM + n]);
            h[4] = __float2half_rn(se[(size_t)kb * DIM + n + 8]);
            h[5] = __float2half_rn(se[(size_t)(kb + 1) * DIM + n + 8]);
            h[6] = __float2half_rn(se[(size_t)(kb + 8) * DIM + n + 8]);
            h[7] = __float2half_rn(se[(size_t)(kb + 9) * DIM + n + 8]);
        } else {
            const __half* se = g_Mh + (size_t)e * KD * DIM;
            h[0] = se[(size_t)kb * DIM + n];
            h[1] = se[(size_t)(kb + 1) * DIM + n];
            h[2] = se[(size_t)(kb + 8) * DIM + n];
            h[3] = se[(size_t)(kb + 9) * DIM + n];
            h[4] = se[(size_t)kb * DIM + n + 8];
            h[5] = se[(size_t)(kb + 1) * DIM + n + 8];
            h[6] = se[(size_t)(kb + 8) * DIM + n + 8];
            h[7] = se[(size_t)(kb + 9) * DIM + n + 8];
        }
        *(uint4*)(tile + ks * 2048 + tp * 256 + lane * 8) = *(uint4*)h;
    }
}

// ---------------- router (logits, softmax, top-2, scatter lists) ----------------
__global__ void router_kernel(const float* __restrict__ x,
                              const float* __restrict__ wr) {
    __shared__ float swr[NEXP][DIM];
    __shared__ float s_p[NEXP];
    __shared__ float s_z;

    int tid = threadIdx.x;
    for (int i = tid; i < NEXP * DIM; i += 256) {
        int d = i >> 3, e = i & 7;
        swr[e][d] = wr[i];
    }
    if (tid < NEXP) s_p[tid] = 0.f;
    if (tid == 0)   s_z = 0.f;
    __syncthreads();

    int lane = tid & 31, warp = tid >> 5;
    int t = blockIdx.x * 8 + warp;

    float acc[NEXP];
#pragma unroll
    for (int e = 0; e < NEXP; e++) acc[e] = 0.f;

    const float4* xr = (const float4*)(x + (size_t)t * DIM);
    for (int c = lane; c < DIM / 4; c += 32) {
        float4 xv = xr[c];
#pragma unroll
        for (int e = 0; e < NEXP; e++) {
            float4 wv = *(const float4*)&swr[e][c * 4];
            acc[e] += xv.x * wv.x + xv.y * wv.y + xv.z * wv.z + xv.w * wv.w;
        }
    }
#pragma unroll
    for (int e = 0; e < NEXP; e++)
        for (int o = 16; o; o >>= 1) acc[e] += __shfl_xor_sync(0xffffffffu, acc[e], o);

    if (lane == 0) {
        float m = acc[0];
#pragma unroll
        for (int e = 1; e < NEXP; e++) m = fmaxf(m, acc[e]);
        float p[NEXP], se = 0.f;
#pragma unroll
        for (int e = 0; e < NEXP; e++) { p[e] = expf(acc[e] - m); se += p[e]; }
        float inv = 1.f / se;
#pragma unroll
        for (int e = 0; e < NEXP; e++) p[e] *= inv;
        float lse = m + logf(se);

        int e0 = 0;
#pragma unroll
        for (int e = 1; e < NEXP; e++) if (p[e] > p[e0]) e0 = e;
        int e1 = (e0 == 0) ? 1 : 0;
#pragma unroll
        for (int e = 0; e < NEXP; e++) if (e != e0 && p[e] > p[e1]) e1 = e;

        float w0 = p[e0], w1v = p[e1], s = w0 + w1v;
        w0 /= s; w1v /= s;

        int pos = atomicAdd(&g_count[e0], 1);
        g_list[e0 * NUM_T + pos] = t;  g_wsel[e0 * NUM_T + pos] = w0;
        pos = atomicAdd(&g_count[e1], 1);
        g_list[e1 * NUM_T + pos] = t;  g_wsel[e1 * NUM_T + pos] = w1v;

        atomicAdd(&s_z, lse * lse);
#pragma unroll
        for (int e = 0; e < NEXP; e++) atomicAdd(&s_p[e], p[e]);
    }
    __syncthreads();
    if (tid < NEXP) atomicAdd(&g_psum[tid], s_p[tid]);
    if (tid == 0)   atomicAdd(&g_zsum, s_z);
}

// ---------------- aux-loss outputs ----------------
__global__ void finalize_kernel(float* out_tail) {
    if (threadIdx.x == 0) {
        float z = g_zsum / (float)NUM_T;
        float lb = 0.f;
#pragma unroll
        for (int e = 0; e < NEXP; e++) {
            float f = (float)g_count[e] / (float)(NUM_T * 2);
            lb += f * (g_psum[e] / (float)NUM_T);
        }
        lb *= (float)NEXP;
        out_tail[0] = z;
        out_tail[1] = lb;
#pragma unroll
        for (int e = 0; e < NEXP; e++)
            out_tail[2 + e] = (float)g_count[e] / (float)(NUM_T * 2);
    }
}

// ---------------- fp16 tensor-core GEMM (m16n8k16), fragment-order B ----------------
// MODE 3: M_e = W1_e @ W2_e            (dense, fp16 store to g_Mh)
// MODE 4: out[tok] += wsel * (gather(x) @ M_e)   (vector-red scatter)
template<int KD, int MODE>
__global__ __launch_bounds__(256) void moe_gemm(float* out) {
    constexpr int ITERS = KD / BKH;
    const int e   = blockIdx.z;
    const int cnt = (MODE == 3) ? DIM : g_count[e];
    const int m0  = blockIdx.x * BM;
    if (m0 >= cnt) return;
    const int n0  = blockIdx.y * BN;

    extern __shared__ __half smem[];
    __half* sA = smem;
    __half* sB = smem + 2 * SA_SZ;

    const int tid = threadIdx.x, lane = tid & 31, warp = tid >> 5;

    // ---- A row pointers (gathered for MODE 4; clamped for partial tiles) ----
    const __half* aptr[4];
#pragma unroll
    for (int i = 0; i < 4; i++) {
        int rr = m0 + (tid >> 3) + i * 32;
        if (MODE == 3) {
            aptr[i] = g_W1h + (size_t)rr * (NEXP * DFFN) + (size_t)e * DFFN
                    + (tid & 7) * 8;
        } else {
            if (rr >= cnt) rr = cnt - 1;
            int tok = g_list[e * NUM_T + rr];
            aptr[i] = g_Xh + (size_t)tok * DIM + (tid & 7) * 8;
        }
    }
    // ---- B fragment tile base (contiguous 16KB tiles per BKH step) ----
    const __half* Bt = (MODE == 3)
        ? (g_W2B + (size_t)((e * 8 + blockIdx.y) * ITERS) * 8192)
        : (g_MB  + (size_t)((e * 8 + blockIdx.y) * ITERS) * 8192);

    auto load_stage = [&](int it, int s) {
        __half* sAs = sA + s * SA_SZ;
        __half* sBs = sB + s * SB_SZ;
        int k0 = it * BKH;
#pragma unroll
        for (int i = 0; i < 4; i++)
            cpa16(sAs + ((tid >> 3) + i * 32) * SA_STRIDE + (tid & 7) * 8,
                  aptr[i] + k0);
        const __half* bsrc = Bt + (size_t)it * 8192;
#pragma unroll
        for (int p = 0; p < 4; p++)
            cpa16(sBs + p * 2048 + tid * 8, bsrc + p * 2048 + tid * 8);
        cpa_commit();
    };

    float acc[2][8][4];
#pragma unroll
    for (int a = 0; a < 2; a++)
#pragma unroll
        for (int b = 0; b < 8; b++)
#pragma unroll
            for (int c = 0; c < 4; c++) acc[a][b][c] = 0.f;

    const int wm  = (warp & 3) * 32;
    const int wng = (warp >> 2);          // n-group 0/1 -> n offset wng*64

    auto compute_stage = [&](int s) {
        const __half* sAs = sA + s * SA_SZ;
        const __half* sBs = sB + s * SB_SZ;
#pragma unroll
        for (int ks = 0; ks < 4; ks++) {
            uint32_t afr[2][4];
#pragma unroll
            for (int tm = 0; tm < 2; tm++) {
                const __half* p = sAs + (wm + tm * 16 + (lane & 15)) * SA_STRIDE
                                + ks * 16 + (lane >> 4) * 8;
                ldsm4(afr[tm], p);
            }
            uint4 bfr[4];
            const __half* bq = sBs + ks * 2048 + wng * 1024 + lane * 8;
#pragma unroll
            for (int tp = 0; tp < 4; tp++)
                bfr[tp] = *(const uint4*)(bq + tp * 256);
#pragma unroll
            for (int tm = 0; tm < 2; tm++)
#pragma unroll
                for (int tn = 0; tn < 8; tn++) {
                    const uint32_t* bb = (tn & 1) ? &bfr[tn >> 1].z : &bfr[tn >> 1].x;
                    mma16(acc[tm][tn], afr[tm], bb);
                }
        }
    };

    load_stage(0, 0);
    load_stage(1, 1);
    cpa_wait<1>();
    __syncthreads();
#pragma unroll 1
    for (int it = 0; it < ITERS; ++it) {
        compute_stage(it & 1);
        __syncthreads();
        if (it + 2 < ITERS) {
            load_stage(it + 2, it & 1);
            cpa_wait<1>();
            __syncthreads();
        } else if (it + 1 < ITERS) {
            cpa_wait<0>();
            __syncthreads();
        }
    }

    // ---- epilogue ----
#pragma unroll
    for (int tm = 0; tm < 2; tm++) {
#pragma unroll
        for (int half = 0; half < 2; half++) {
            int r  = wm + tm * 16 + (lane >> 2) + half * 8;
            int gr = m0 + r;
            if (gr < cnt) {
                if (MODE == 3) {
                    __half* mrow = g_Mh + (size_t)e * DIM * DIM
                                 + (size_t)gr * DIM + n0 + wng * 64;
#pragma unroll
                    for (int tn = 0; tn < 8; tn++) {
                        int c = tn * 8 + (lane & 3) * 2;
                        __half2 h = __floats2half2_rn(acc[tm][tn][half * 2 + 0],
                                                      acc[tm][tn][half * 2 + 1]);
                        *(__half2*)(mrow + c) = h;
                    }
                } else {
                    float w   = g_wsel[e * NUM_T + gr];
                    int   tok = g_list[e * NUM_T + gr];
                    float* orow = out + (size_t)tok * DIM + n0 + wng * 64;
#pragma unroll
                    for (int tn = 0; tn < 8; tn++) {
                        int c = tn * 8 + (lane & 3) * 2;
                        red2(orow + c,
                             w * acc[tm][tn][half * 2 + 0],
                             w * acc[tm][tn][half * 2 + 1]);
                    }
                }
            }
        }
    }
}

// ---------------- launch ----------------
extern "C" void kernel_launch(void* const* d_in, const int* in_sizes, int n_in,
                              void* d_out, int out_size) {
    const float* x  = (const float*)d_in[0];
    const float* wr = (const float*)d_in[1];
    const float* w1 = (const float*)d_in[2];
    const float* w2 = (const float*)d_in[3];
    float* out = (float*)d_out;

    cudaFuncSetAttribute(moe_gemm<DFFN, 3>,
                         cudaFuncAttributeMaxDynamicSharedMemorySize, SMEM_BYTES);
    cudaFuncSetAttribute(moe_gemm<DIM, 4>,
                         cudaFuncAttributeMaxDynamicSharedMemorySize, SMEM_BYTES);

    cudaMemsetAsync(out, 0, (size_t)OUT_MAT * sizeof(float), 0);
    zero_kernel<<<1, 32>>>();
    convert_kernel<<<24576, 256>>>((const float4*)x, (const float4*)w1);
    frag_pack<DFFN, 0><<<NEXP * 8 * (DFFN / 64), 256>>>(w2);   // w2 -> g_W2B
    router_kernel<<<NUM_T / 8, 256>>>(x, wr);
    finalize_kernel<<<1, 32>>>(out + OUT_MAT);

    // GEMM1: M_e = W1_e @ W2_e   (M=1024, N=1024, K=2048 per expert)
    moe_gemm<DFFN, 3><<<dim3(DIM / BM, DIM / BN, NEXP), 256, SMEM_BYTES>>>(nullptr);
    // repack M into GEMM2 B tiles (g_Mh -> g_MB)
    frag_pack<DIM, 1><<<NEXP * 8 * (DIM / 64), 256>>>(nullptr);
    // GEMM2: out[tok] += wsel * (x_gathered @ M_e)   (N=1024, K=1024)
    moe_gemm<DIM, 4><<<dim3(NUM_T / BM, DIM / BN, NEXP), 256, SMEM_BYTES>>>(out);
}

// round 7
// speedup vs baseline: 3.1063x; 1.1309x over previous
#include <cuda_runtime.h>
#include <cuda_fp16.h>
#include <cstdint>

#define NUM_T 8192
#define DIM   1024
#define NEXP  8
#define DFFN  2048
#define OUT_MAT (NUM_T * DIM)

#define BM 128
#define BN 128
#define BKH 64                          // K elements (halfs) per stage
#define SA_STRIDE 72                    // halfs, conflict-free ldmatrix
#define SA_SZ (BM * SA_STRIDE)          // 9216 halfs = 18 KB
#define SB_SZ 8192                      // halfs = 16 KB (frag tile)
#define SMEM_BYTES (2 * (SA_SZ + SB_SZ) * 2)   // 69632 B

// ---------------- scratch (device globals; no allocations allowed) ----------------
__device__ __half g_Xh [NUM_T * DIM];             // 16 MB fp16 x (row-major)
__device__ __half g_W1h[DIM * NEXP * DFFN];       // 32 MB fp16 w1 (row-major)
__device__ __half g_W2B[NEXP * 8 * 32 * 8192];    // 32 MB w2 fragment tiles (GEMM1 B)
__device__ __half g_Mh [NEXP * DIM * DIM];        // 16 MB fused expert matrices
__device__ __half g_MB [NEXP * 8 * 16 * 8192];    // 16 MB M fragment tiles (GEMM2 B)
__device__ int    g_list[NEXP * NUM_T];
__device__ float  g_wsel[NEXP * NUM_T];
__device__ int    g_count[NEXP];
__device__ float  g_psum[NEXP];
__device__ float  g_zsum;

// ---------------- small helpers ----------------
__device__ __forceinline__ unsigned cvta_s(const void* p) {
    return (unsigned)__cvta_generic_to_shared((void*)p);
}
__device__ __forceinline__ void cpa16(void* sdst, const void* gsrc) {
    asm volatile("cp.async.cg.shared.global [%0], [%1], 16;"
                 :: "r"(cvta_s(sdst)), "l"(gsrc));
}
__device__ __forceinline__ void cpa_commit() {
    asm volatile("cp.async.commit_group;");
}
template<int N> __device__ __forceinline__ void cpa_wait() {
    asm volatile("cp.async.wait_group %0;" :: "n"(N));
}
__device__ __forceinline__ void ldsm4(uint32_t* a, const void* p) {
    asm volatile("ldmatrix.sync.aligned.m8n8.x4.shared.b16 {%0,%1,%2,%3}, [%4];"
                 : "=r"(a[0]), "=r"(a[1]), "=r"(a[2]), "=r"(a[3])
                 : "r"(cvta_s(p)));
}
__device__ __forceinline__ void mma16(float* c, const uint32_t* a, const uint32_t* b) {
    asm volatile("mma.sync.aligned.m16n8k16.row.col.f32.f16.f16.f32 "
                 "{%0,%1,%2,%3}, {%4,%5,%6,%7}, {%8,%9}, {%0,%1,%2,%3};"
                 : "+f"(c[0]), "+f"(c[1]), "+f"(c[2]), "+f"(c[3])
                 : "r"(a[0]), "r"(a[1]), "r"(a[2]), "r"(a[3]),
                   "r"(b[0]), "r"(b[1]));
}
__device__ __forceinline__ void red2(float* p, float a, float b) {
    asm volatile("red.global.v2.f32.add [%0], {%1, %2};"
                 :: "l"(p), "f"(a), "f"(b) : "memory");
}

// ---------------- kernel 0: zero the tiny accumulators ----------------
__global__ void zero_kernel() {
    int t = threadIdx.x;
    if (t < NEXP) { g_count[t] = 0; g_psum[t] = 0.f; }
    if (t == 0)   { g_zsum = 0.f; }
}

// ---------------- kernel 1: fp16-round x and w1 into scratch (row-major) ----------------
__global__ void convert_kernel(const float4* __restrict__ x,
                               const float4* __restrict__ w1) {
    const unsigned NX = (NUM_T * DIM) / 4;          // 2097152
    unsigned i = blockIdx.x * 256u + threadIdx.x;   // total NX + NW1 = 6291456
    float4 v; __half* dst;
    if (i < NX) { v = x[i];       dst = g_Xh  + (size_t)i * 4; }
    else        { v = w1[i - NX]; dst = g_W1h + (size_t)(i - NX) * 4; }
    __half2 h0 = __floats2half2_rn(v.x, v.y);
    __half2 h1 = __floats2half2_rn(v.z, v.w);
    uint2 o;
    o.x = *(uint32_t*)&h0;
    o.y = *(uint32_t*)&h1;
    *(uint2*)dst = o;
}

// ---------------- fragment packer (smem-staged, coalesced) --------------------------
// WHICH=0: src = w2 (fp32 kernel arg) -> g_W2B ; WHICH=1: src = g_Mh (fp16) -> g_MB
// tile b = (e*8 + nt)*KT + kt covers k in [kt*64, kt*64+64), n in [nt*128, nt*128+128)
// layout: [ks(4)][tp(8)][lane(32)][8 halfs]; per lane, per tp: two n8-tile frags
//   frag(tn) = {B[kb][n], B[kb+1][n], B[kb+8][n], B[kb+9][n]},
//   kb = kt*64 + ks*16 + 2*(lane&3), n = nt*128 + tp*16 + (tn&1)*8 + (lane>>2)
template<int KD, int WHICH>
__global__ __launch_bounds__(256) void frag_pack(const float* __restrict__ w2src) {
    __shared__ __half sh[64][136];      // padded: row stride 272 B, 16B-aligned
    constexpr int KT = KD / 64;
    int b  = blockIdx.x;
    int kt = b % KT;
    int nt = (b / KT) & 7;
    int e  = b / (KT * 8);
    int tid = threadIdx.x, lane = tid & 31, slot = tid >> 5;

    // ---- stage 64x128 block into smem (coalesced) ----
    if (WHICH == 0) {
        const float* se = w2src + (size_t)e * KD * DIM + (size_t)(kt * 64) * DIM
                        + nt * 128;
#pragma unroll
        for (int i = tid; i < 2048; i += 256) {      // 2048 float4
            int r = i >> 5, c4 = i & 31;
            float4 v = *(const float4*)(se + (size_t)r * DIM + c4 * 4);
            __half2 h0 = __floats2half2_rn(v.x, v.y);
            __half2 h1 = __floats2half2_rn(v.z, v.w);
            uint2 o; o.x = *(uint32_t*)&h0; o.y = *(uint32_t*)&h1;
            *(uint2*)&sh[r][c4 * 4] = o;
        }
    } else {
        const __half* se = g_Mh + (size_t)e * KD * DIM + (size_t)(kt * 64) * DIM
                         + nt * 128;
#pragma unroll
        for (int i = tid; i < 1024; i += 256) {      // 1024 x 8 halfs
            int r = i >> 4, c8 = i & 15;
            uint4 v = *(const uint4*)(se + (size_t)r * DIM + c8 * 8);
            *(uint4*)&sh[r][c8 * 8] = v;
        }
    }
    __syncthreads();

    // ---- emit fragment tile (coalesced 16B stores) ----
    __half* tile = ((WHICH == 0) ? g_W2B : g_MB) + (size_t)b * 8192;
#pragma unroll
    for (int j = 0; j < 4; j++) {
        int idx = slot * 4 + j;           // 0..31 -> (ks, tp)
        int ks = idx >> 3, tp = idx & 7;
        int kb = ks * 16 + 2 * (lane & 3);
        int n  = tp * 16 + (lane >> 2);
        __half h[8];
        h[0] = sh[kb][n];     h[1] = sh[kb + 1][n];
        h[2] = sh[kb + 8][n]; h[3] = sh[kb + 9][n];
        h[4] = sh[kb][n + 8];     h[5] = sh[kb + 1][n + 8];
        h[6] = sh[kb + 8][n + 8]; h[7] = sh[kb + 9][n + 8];
        *(uint4*)(tile + ks * 2048 + tp * 256 + lane * 8) = *(uint4*)h;
    }
}

// ---------------- router: 4 tokens per warp ----------------
__global__ __launch_bounds__(256) void router_kernel(const float* __restrict__ x,
                                                     const float* __restrict__ wr) {
    __shared__ float swr[NEXP][DIM];
    __shared__ float s_p[NEXP];
    __shared__ float s_z;

    int tid = threadIdx.x;
    for (int i = tid; i < NEXP * DIM; i += 256) {
        int d = i >> 3, e = i & 7;
        swr[e][d] = wr[i];
    }
    if (tid < NEXP) s_p[tid] = 0.f;
    if (tid == 0)   s_z = 0.f;
    __syncthreads();

    int lane = tid & 31, warp = tid >> 5;
    int t0 = blockIdx.x * 32 + warp * 4;            // 4 tokens per warp

    float acc[4][NEXP];
#pragma unroll
    for (int tt = 0; tt < 4; tt++)
#pragma unroll
        for (int e = 0; e < NEXP; e++) acc[tt][e] = 0.f;

    const float4* xr[4];
#pragma unroll
    for (int tt = 0; tt < 4; tt++)
        xr[tt] = (const float4*)(x + (size_t)(t0 + tt) * DIM);

    for (int c = lane; c < DIM / 4; c += 32) {
        float4 xv[4];
#pragma unroll
        for (int tt = 0; tt < 4; tt++) xv[tt] = xr[tt][c];
#pragma unroll
        for (int e = 0; e < NEXP; e++) {
            float4 wv = *(const float4*)&swr[e][c * 4];
#pragma unroll
            for (int tt = 0; tt < 4; tt++)
                acc[tt][e] += xv[tt].x * wv.x + xv[tt].y * wv.y
                            + xv[tt].z * wv.z + xv[tt].w * wv.w;
        }
    }
#pragma unroll
    for (int tt = 0; tt < 4; tt++)
#pragma unroll
        for (int e = 0; e < NEXP; e++)
            for (int o = 16; o; o >>= 1)
                acc[tt][e] += __shfl_xor_sync(0xffffffffu, acc[tt][e], o);

    if (lane < 4) {                                  // lane tt owns token t0+tt
        int t = t0 + lane;
        float m = acc[lane][0];
#pragma unroll
        for (int e = 1; e < NEXP; e++) m = fmaxf(m, acc[lane][e]);
        float p[NEXP], se = 0.f;
#pragma unroll
        for (int e = 0; e < NEXP; e++) { p[e] = expf(acc[lane][e] - m); se += p[e]; }
        float inv = 1.f / se;
#pragma unroll
        for (int e = 0; e < NEXP; e++) p[e] *= inv;
        float lse = m + logf(se);

        int e0 = 0;
#pragma unroll
        for (int e = 1; e < NEXP; e++) if (p[e] > p[e0]) e0 = e;
        int e1 = (e0 == 0) ? 1 : 0;
#pragma unroll
        for (int e = 0; e < NEXP; e++) if (e != e0 && p[e] > p[e1]) e1 = e;

        float w0 = p[e0], w1v = p[e1], s = w0 + w1v;
        w0 /= s; w1v /= s;

        int pos = atomicAdd(&g_count[e0], 1);
        g_list[e0 * NUM_T + pos] = t;  g_wsel[e0 * NUM_T + pos] = w0;
        pos = atomicAdd(&g_count[e1], 1);
        g_list[e1 * NUM_T + pos] = t;  g_wsel[e1 * NUM_T + pos] = w1v;

        atomicAdd(&s_z, lse * lse);
#pragma unroll
        for (int e = 0; e < NEXP; e++) atomicAdd(&s_p[e], p[e]);
    }
    __syncthreads();
    if (tid < NEXP) atomicAdd(&g_psum[tid], s_p[tid]);
    if (tid == 0)   atomicAdd(&g_zsum, s_z);
}

// ---------------- aux-loss outputs ----------------
__global__ void finalize_kernel(float* out_tail) {
    if (threadIdx.x == 0) {
        float z = g_zsum / (float)NUM_T;
        float lb = 0.f;
#pragma unroll
        for (int e = 0; e < NEXP; e++) {
            float f = (float)g_count[e] / (float)(NUM_T * 2);
            lb += f * (g_psum[e] / (float)NUM_T);
        }
        lb *= (float)NEXP;
        out_tail[0] = z;
        out_tail[1] = lb;
#pragma unroll
        for (int e = 0; e < NEXP; e++)
            out_tail[2 + e] = (float)g_count[e] / (float)(NUM_T * 2);
    }
}

// ---------------- fp16 tensor-core GEMM (m16n8k16), fragment-order B ----------------
// MODE 3: M_e = W1_e @ W2_e            (dense, fp16 store to g_Mh)
// MODE 4: out[tok] += wsel * (gather(x) @ M_e)   (vector-red scatter)
template<int KD, int MODE>
__global__ __launch_bounds__(256, 2) void moe_gemm(float* out) {
    constexpr int ITERS = KD / BKH;
    const int e   = blockIdx.z;
    const int cnt = (MODE == 3) ? DIM : g_count[e];
    const int m0  = blockIdx.x * BM;
    if (m0 >= cnt) return;
    const int n0  = blockIdx.y * BN;

    extern __shared__ __half smem[];
    __half* sA = smem;
    __half* sB = smem + 2 * SA_SZ;

    const int tid = threadIdx.x, lane = tid & 31, warp = tid >> 5;

    // ---- A row pointers (gathered for MODE 4; clamped for partial tiles) ----
    const __half* aptr[4];
#pragma unroll
    for (int i = 0; i < 4; i++) {
        int rr = m0 + (tid >> 3) + i * 32;
        if (MODE == 3) {
            aptr[i] = g_W1h + (size_t)rr * (NEXP * DFFN) + (size_t)e * DFFN
                    + (tid & 7) * 8;
        } else {
            if (rr >= cnt) rr = cnt - 1;
            int tok = g_list[e * NUM_T + rr];
            aptr[i] = g_Xh + (size_t)tok * DIM + (tid & 7) * 8;
        }
    }
    // ---- B fragment tile base (contiguous 16KB tiles per BKH step) ----
    const __half* Bt = (MODE == 3)
        ? (g_W2B + (size_t)((e * 8 + blockIdx.y) * ITERS) * 8192)
        : (g_MB  + (size_t)((e * 8 + blockIdx.y) * ITERS) * 8192);

    auto load_stage = [&](int it, int s) {
        __half* sAs = sA + s * SA_SZ;
        __half* sBs = sB + s * SB_SZ;
        int k0 = it * BKH;
#pragma unroll
        for (int i = 0; i < 4; i++)
            cpa16(sAs + ((tid >> 3) + i * 32) * SA_STRIDE + (tid & 7) * 8,
                  aptr[i] + k0);
        const __half* bsrc = Bt + (size_t)it * 8192;
#pragma unroll
        for (int p = 0; p < 4; p++)
            cpa16(sBs + p * 2048 + tid * 8, bsrc + p * 2048 + tid * 8);
        cpa_commit();
    };

    float acc[2][8][4];
#pragma unroll
    for (int a = 0; a < 2; a++)
#pragma unroll
        for (int b = 0; b < 8; b++)
#pragma unroll
            for (int c = 0; c < 4; c++) acc[a][b][c] = 0.f;

    const int wm  = (warp & 3) * 32;
    const int wng = (warp >> 2);          // n-group 0/1 -> n offset wng*64

    auto compute_stage = [&](int s) {
        const __half* sAs = sA + s * SA_SZ;
        const __half* sBs = sB + s * SB_SZ;
#pragma unroll
        for (int ks = 0; ks < 4; ks++) {
            uint32_t afr[2][4];
#pragma unroll
            for (int tm = 0; tm < 2; tm++) {
                const __half* p = sAs + (wm + tm * 16 + (lane & 15)) * SA_STRIDE
                                + ks * 16 + (lane >> 4) * 8;
                ldsm4(afr[tm], p);
            }
            uint4 bfr[4];
            const __half* bq = sBs + ks * 2048 + wng * 1024 + lane * 8;
#pragma unroll
            for (int tp = 0; tp < 4; tp++)
                bfr[tp] = *(const uint4*)(bq + tp * 256);
#pragma unroll
            for (int tm = 0; tm < 2; tm++)
#pragma unroll
                for (int tn = 0; tn < 8; tn++) {
                    const uint32_t* bb = (tn & 1) ? &bfr[tn >> 1].z : &bfr[tn >> 1].x;
                    mma16(acc[tm][tn], afr[tm], bb);
                }
        }
    };

    load_stage(0, 0);
    load_stage(1, 1);
    cpa_wait<1>();
    __syncthreads();
#pragma unroll 1
    for (int it = 0; it < ITERS; ++it) {
        compute_stage(it & 1);
        __syncthreads();
        if (it + 2 < ITERS) {
            load_stage(it + 2, it & 1);
            cpa_wait<1>();
            __syncthreads();
        } else if (it + 1 < ITERS) {
            cpa_wait<0>();
            __syncthreads();
        }
    }

    // ---- epilogue ----
#pragma unroll
    for (int tm = 0; tm < 2; tm++) {
#pragma unroll
        for (int half = 0; half < 2; half++) {
            int r  = wm + tm * 16 + (lane >> 2) + half * 8;
            int gr = m0 + r;
            if (gr < cnt) {
                if (MODE == 3) {
                    __half* mrow = g_Mh + (size_t)e * DIM * DIM
                                 + (size_t)gr * DIM + n0 + wng * 64;
#pragma unroll
                    for (int tn = 0; tn < 8; tn++) {
                        int c = tn * 8 + (lane & 3) * 2;
                        __half2 h = __floats2half2_rn(acc[tm][tn][half * 2 + 0],
                                                      acc[tm][tn][half * 2 + 1]);
                        *(__half2*)(mrow + c) = h;
                    }
                } else {
                    float w   = g_wsel[e * NUM_T + gr];
                    int   tok = g_list[e * NUM_T + gr];
                    float* orow = out + (size_t)tok * DIM + n0 + wng * 64;
#pragma unroll
                    for (int tn = 0; tn < 8; tn++) {
                        int c = tn * 8 + (lane & 3) * 2;
                        red2(orow + c,
                             w * acc[tm][tn][half * 2 + 0],
                             w * acc[tm][tn][half * 2 + 1]);
                    }
                }
            }
        }
    }
}

// ---------------- launch ----------------
extern "C" void kernel_launch(void* const* d_in, const int* in_sizes, int n_in,
                              void* d_out, int out_size) {
    const float* x  = (const float*)d_in[0];
    const float* wr = (const float*)d_in[1];
    const float* w1 = (const float*)d_in[2];
    const float* w2 = (const float*)d_in[3];
    float* out = (float*)d_out;

    cudaFuncSetAttribute(moe_gemm<DFFN, 3>,
                         cudaFuncAttributeMaxDynamicSharedMemorySize, SMEM_BYTES);
    cudaFuncSetAttribute(moe_gemm<DIM, 4>,
                         cudaFuncAttributeMaxDynamicSharedMemorySize, SMEM_BYTES);

    cudaMemsetAsync(out, 0, (size_t)OUT_MAT * sizeof(float), 0);
    zero_kernel<<<1, 32>>>();
    convert_kernel<<<24576, 256>>>((const float4*)x, (const float4*)w1);
    frag_pack<DFFN, 0><<<NEXP * 8 * (DFFN / 64), 256>>>(w2);   // w2 -> g_W2B
    router_kernel<<<NUM_T / 32, 256>>>(x, wr);
    finalize_kernel<<<1, 32>>>(out + OUT_MAT);

    // GEMM1: M_e = W1_e @ W2_e   (M=1024, N=1024, K=2048 per expert)
    moe_gemm<DFFN, 3><<<dim3(DIM / BM, DIM / BN, NEXP), 256, SMEM_BYTES>>>(nullptr);
    // repack M into GEMM2 B tiles (g_Mh -> g_MB)
    frag_pack<DIM, 1><<<NEXP * 8 * (DIM / 64), 256>>>(nullptr);
    // GEMM2: out[tok] += wsel * (x_gathered @ M_e)   (N=1024, K=1024)
    moe_gemm<DIM, 4><<<dim3(NUM_T / BM, DIM / BN, NEXP), 256, SMEM_BYTES>>>(out);
}

// round 8
// speedup vs baseline: 3.1827x; 1.0246x over previous
#include <cuda_runtime.h>
#include <cuda_fp16.h>
#include <cstdint>

#define NUM_T 8192
#define DIM   1024
#define NEXP  8
#define DFFN  2048
#define OUT_MAT (NUM_T * DIM)

#define BM 128
#define BN 128
#define BKH 64                          // K elements (halfs) per stage
#define SA_STRIDE 72                    // halfs, conflict-free ldmatrix
#define SA_SZ (BM * SA_STRIDE)          // 9216 halfs = 18 KB
#define SB_SZ 8192                      // halfs = 16 KB (frag tile)
#define SMEM_BYTES (2 * (SA_SZ + SB_SZ) * 2)   // 69632 B ( == 128*136*2 for epilogue )

// ---------------- scratch (device globals; no allocations allowed) ----------------
__device__ __half g_Xh [NUM_T * DIM];             // 16 MB fp16 x (row-major)
__device__ __half g_W1h[DIM * NEXP * DFFN];       // 32 MB fp16 w1 (row-major)
__device__ __half g_W2B[NEXP * 8 * 32 * 8192];    // 32 MB w2 fragment tiles (GEMM1 B)
__device__ __half g_MB [NEXP * 8 * 16 * 8192];    // 16 MB M fragment tiles (GEMM2 B)
__device__ int    g_list[NEXP * NUM_T];
__device__ float  g_wsel[NEXP * NUM_T];
__device__ int    g_count[NEXP];
__device__ float  g_psum[NEXP];
__device__ float  g_zsum;

// ---------------- small helpers ----------------
__device__ __forceinline__ unsigned cvta_s(const void* p) {
    return (unsigned)__cvta_generic_to_shared((void*)p);
}
__device__ __forceinline__ void cpa16(void* sdst, const void* gsrc) {
    asm volatile("cp.async.cg.shared.global [%0], [%1], 16;"
                 :: "r"(cvta_s(sdst)), "l"(gsrc));
}
__device__ __forceinline__ void cpa_commit() {
    asm volatile("cp.async.commit_group;");
}
template<int N> __device__ __forceinline__ void cpa_wait() {
    asm volatile("cp.async.wait_group %0;" :: "n"(N));
}
__device__ __forceinline__ void ldsm4(uint32_t* a, const void* p) {
    asm volatile("ldmatrix.sync.aligned.m8n8.x4.shared.b16 {%0,%1,%2,%3}, [%4];"
                 : "=r"(a[0]), "=r"(a[1]), "=r"(a[2]), "=r"(a[3])
                 : "r"(cvta_s(p)));
}
__device__ __forceinline__ void mma16(float* c, const uint32_t* a, const uint32_t* b) {
    asm volatile("mma.sync.aligned.m16n8k16.row.col.f32.f16.f16.f32 "
                 "{%0,%1,%2,%3}, {%4,%5,%6,%7}, {%8,%9}, {%0,%1,%2,%3};"
                 : "+f"(c[0]), "+f"(c[1]), "+f"(c[2]), "+f"(c[3])
                 : "r"(a[0]), "r"(a[1]), "r"(a[2]), "r"(a[3]),
                   "r"(b[0]), "r"(b[1]));
}
__device__ __forceinline__ void red2(float* p, float a, float b) {
    asm volatile("red.global.v2.f32.add [%0], {%1, %2};"
                 :: "l"(p), "f"(a), "f"(b) : "memory");
}

// ---------------- kernel 0: zero the tiny accumulators ----------------
__global__ void zero_kernel() {
    int t = threadIdx.x;
    if (t < NEXP) { g_count[t] = 0; g_psum[t] = 0.f; }
    if (t == 0)   { g_zsum = 0.f; }
}

// ---------------- kernel 1: fp16-round x and w1 into scratch (row-major) ----------------
__global__ void convert_kernel(const float4* __restrict__ x,
                               const float4* __restrict__ w1) {
    const unsigned NX = (NUM_T * DIM) / 4;          // 2097152
    unsigned i = blockIdx.x * 256u + threadIdx.x;   // total NX + NW1 = 6291456
    float4 v; __half* dst;
    if (i < NX) { v = x[i];       dst = g_Xh  + (size_t)i * 4; }
    else        { v = w1[i - NX]; dst = g_W1h + (size_t)(i - NX) * 4; }
    __half2 h0 = __floats2half2_rn(v.x, v.y);
    __half2 h1 = __floats2half2_rn(v.z, v.w);
    uint2 o;
    o.x = *(uint32_t*)&h0;
    o.y = *(uint32_t*)&h1;
    *(uint2*)dst = o;
}

// ---------------- fragment packer for w2 (smem-staged, coalesced) --------------------
// tile b = (e*8 + nt)*KT + kt covers k in [kt*64, kt*64+64), n in [nt*128, nt*128+128)
// layout: [ks(4)][tp(8)][lane(32)][8 halfs]; per lane, per tp: two n8-tile frags
//   frag(tn) = {B[kb][n], B[kb+1][n], B[kb+8][n], B[kb+9][n]},
//   kb = kt*64 + ks*16 + 2*(lane&3), n = nt*128 + tp*16 + (tn&1)*8 + (lane>>2)
__global__ __launch_bounds__(256) void frag_pack_w2(const float* __restrict__ w2src) {
    __shared__ __half sh[64][136];      // padded: row stride 272 B
    constexpr int KT = DFFN / 64;
    int b  = blockIdx.x;
    int kt = b % KT;
    int nt = (b / KT) & 7;
    int e  = b / (KT * 8);
    int tid = threadIdx.x, lane = tid & 31, slot = tid >> 5;

    const float* se = w2src + (size_t)e * DFFN * DIM + (size_t)(kt * 64) * DIM
                    + nt * 128;
#pragma unroll
    for (int i = tid; i < 2048; i += 256) {      // 2048 float4
        int r = i >> 5, c4 = i & 31;
        float4 v = *(const float4*)(se + (size_t)r * DIM + c4 * 4);
        __half2 h0 = __floats2half2_rn(v.x, v.y);
        __half2 h1 = __floats2half2_rn(v.z, v.w);
        uint2 o; o.x = *(uint32_t*)&h0; o.y = *(uint32_t*)&h1;
        *(uint2*)&sh[r][c4 * 4] = o;
    }
    __syncthreads();

    __half* tile = g_W2B + (size_t)b * 8192;
#pragma unroll
    for (int j = 0; j < 4; j++) {
        int idx = slot * 4 + j;           // 0..31 -> (ks, tp)
        int ks = idx >> 3, tp = idx & 7;
        int kb = ks * 16 + 2 * (lane & 3);
        int n  = tp * 16 + (lane >> 2);
        __half h[8];
        h[0] = sh[kb][n];     h[1] = sh[kb + 1][n];
        h[2] = sh[kb + 8][n]; h[3] = sh[kb + 9][n];
        h[4] = sh[kb][n + 8];     h[5] = sh[kb + 1][n + 8];
        h[6] = sh[kb + 8][n + 8]; h[7] = sh[kb + 9][n + 8];
        *(uint4*)(tile + ks * 2048 + tp * 256 + lane * 8) = *(uint4*)h;
    }
}

// ---------------- router: 2 tokens per warp, 512 blocks ----------------
__global__ __launch_bounds__(256) void router_kernel(const float* __restrict__ x,
                                                     const float* __restrict__ wr) {
    __shared__ float swr[NEXP][DIM];
    __shared__ float s_p[NEXP];
    __shared__ float s_z;

    int tid = threadIdx.x;
    for (int i = tid; i < NEXP * DIM; i += 256) {
        int d = i >> 3, e = i & 7;
        swr[e][d] = wr[i];
    }
    if (tid < NEXP) s_p[tid] = 0.f;
    if (tid == 0)   s_z = 0.f;
    __syncthreads();

    int lane = tid & 31, warp = tid >> 5;
    int t0 = blockIdx.x * 16 + warp * 2;            // 2 tokens per warp

    float acc[2][NEXP];
#pragma unroll
    for (int tt = 0; tt < 2; tt++)
#pragma unroll
        for (int e = 0; e < NEXP; e++) acc[tt][e] = 0.f;

    const float4* xr0 = (const float4*)(x + (size_t)t0 * DIM);
    const float4* xr1 = (const float4*)(x + (size_t)(t0 + 1) * DIM);

    for (int c = lane; c < DIM / 4; c += 32) {
        float4 xv0 = xr0[c], xv1 = xr1[c];
#pragma unroll
        for (int e = 0; e < NEXP; e++) {
            float4 wv = *(const float4*)&swr[e][c * 4];
            acc[0][e] += xv0.x * wv.x + xv0.y * wv.y + xv0.z * wv.z + xv0.w * wv.w;
            acc[1][e] += xv1.x * wv.x + xv1.y * wv.y + xv1.z * wv.z + xv1.w * wv.w;
        }
    }
#pragma unroll
    for (int tt = 0; tt < 2; tt++)
#pragma unroll
        for (int e = 0; e < NEXP; e++)
            for (int o = 16; o; o >>= 1)
                acc[tt][e] += __shfl_xor_sync(0xffffffffu, acc[tt][e], o);

    if (lane < 2) {                                  // lane tt owns token t0+tt
        int t = t0 + lane;
        float m = acc[lane][0];
#pragma unroll
        for (int e = 1; e < NEXP; e++) m = fmaxf(m, acc[lane][e]);
        float p[NEXP], se = 0.f;
#pragma unroll
        for (int e = 0; e < NEXP; e++) { p[e] = expf(acc[lane][e] - m); se += p[e]; }
        float inv = 1.f / se;
#pragma unroll
        for (int e = 0; e < NEXP; e++) p[e] *= inv;
        float lse = m + logf(se);

        int e0 = 0;
#pragma unroll
        for (int e = 1; e < NEXP; e++) if (p[e] > p[e0]) e0 = e;
        int e1 = (e0 == 0) ? 1 : 0;
#pragma unroll
        for (int e = 0; e < NEXP; e++) if (e != e0 && p[e] > p[e1]) e1 = e;

        float w0 = p[e0], w1v = p[e1], s = w0 + w1v;
        w0 /= s; w1v /= s;

        int pos = atomicAdd(&g_count[e0], 1);
        g_list[e0 * NUM_T + pos] = t;  g_wsel[e0 * NUM_T + pos] = w0;
        pos = atomicAdd(&g_count[e1], 1);
        g_list[e1 * NUM_T + pos] = t;  g_wsel[e1 * NUM_T + pos] = w1v;

        atomicAdd(&s_z, lse * lse);
#pragma unroll
        for (int e = 0; e < NEXP; e++) atomicAdd(&s_p[e], p[e]);
    }
    __syncthreads();
    if (tid < NEXP) atomicAdd(&g_psum[tid], s_p[tid]);
    if (tid == 0)   atomicAdd(&g_zsum, s_z);
}

// ---------------- aux-loss outputs ----------------
__global__ void finalize_kernel(float* out_tail) {
    if (threadIdx.x == 0) {
        float z = g_zsum / (float)NUM_T;
        float lb = 0.f;
#pragma unroll
        for (int e = 0; e < NEXP; e++) {
            float f = (float)g_count[e] / (float)(NUM_T * 2);
            lb += f * (g_psum[e] / (float)NUM_T);
        }
        lb *= (float)NEXP;
        out_tail[0] = z;
        out_tail[1] = lb;
#pragma unroll
        for (int e = 0; e < NEXP; e++)
            out_tail[2 + e] = (float)g_count[e] / (float)(NUM_T * 2);
    }
}

// ---------------- fp16 tensor-core GEMM (m16n8k16), fragment-order B ----------------
// MODE 3: M_e = W1_e @ W2_e ; epilogue emits fragment tiles straight into g_MB
// MODE 4: out[tok] += wsel * (gather(x) @ M_e)   (vector-red scatter)
template<int KD, int MODE>
__global__ __launch_bounds__(256, 2) void moe_gemm(float* out) {
    constexpr int ITERS = KD / BKH;
    const int e   = blockIdx.z;
    const int cnt = (MODE == 3) ? DIM : g_count[e];
    const int m0  = blockIdx.x * BM;
    if (m0 >= cnt) return;
    const int n0  = blockIdx.y * BN;

    extern __shared__ __half smem[];
    __half* sA = smem;
    __half* sB = smem + 2 * SA_SZ;

    const int tid = threadIdx.x, lane = tid & 31, warp = tid >> 5;

    // ---- A row pointers (gathered for MODE 4; clamped for partial tiles) ----
    const __half* aptr[4];
#pragma unroll
    for (int i = 0; i < 4; i++) {
        int rr = m0 + (tid >> 3) + i * 32;
        if (MODE == 3) {
            aptr[i] = g_W1h + (size_t)rr * (NEXP * DFFN) + (size_t)e * DFFN
                    + (tid & 7) * 8;
        } else {
            if (rr >= cnt) rr = cnt - 1;
            int tok = g_list[e * NUM_T + rr];
            aptr[i] = g_Xh + (size_t)tok * DIM + (tid & 7) * 8;
        }
    }
    // ---- B fragment tile base (contiguous 16KB tiles per BKH step) ----
    const __half* Bt = (MODE == 3)
        ? (g_W2B + (size_t)((e * 8 + blockIdx.y) * ITERS) * 8192)
        : (g_MB  + (size_t)((e * 8 + blockIdx.y) * ITERS) * 8192);

    auto load_stage = [&](int it, int s) {
        __half* sAs = sA + s * SA_SZ;
        __half* sBs = sB + s * SB_SZ;
        int k0 = it * BKH;
#pragma unroll
        for (int i = 0; i < 4; i++)
            cpa16(sAs + ((tid >> 3) + i * 32) * SA_STRIDE + (tid & 7) * 8,
                  aptr[i] + k0);
        const __half* bsrc = Bt + (size_t)it * 8192;
#pragma unroll
        for (int p = 0; p < 4; p++)
            cpa16(sBs + p * 2048 + tid * 8, bsrc + p * 2048 + tid * 8);
        cpa_commit();
    };

    float acc[2][8][4];
#pragma unroll
    for (int a = 0; a < 2; a++)
#pragma unroll
        for (int b = 0; b < 8; b++)
#pragma unroll
            for (int c = 0; c < 4; c++) acc[a][b][c] = 0.f;

    const int wm  = (warp & 3) * 32;
    const int wng = (warp >> 2);          // n-group 0/1 -> n offset wng*64

    auto compute_stage = [&](int s) {
        const __half* sAs = sA + s * SA_SZ;
        const __half* sBs = sB + s * SB_SZ;
#pragma unroll
        for (int ks = 0; ks < 4; ks++) {
            uint32_t afr[2][4];
#pragma unroll
            for (int tm = 0; tm < 2; tm++) {
                const __half* p = sAs + (wm + tm * 16 + (lane & 15)) * SA_STRIDE
                                + ks * 16 + (lane >> 4) * 8;
                ldsm4(afr[tm], p);
            }
            uint4 bfr[4];
            const __half* bq = sBs + ks * 2048 + wng * 1024 + lane * 8;
#pragma unroll
            for (int tp = 0; tp < 4; tp++)
                bfr[tp] = *(const uint4*)(bq + tp * 256);
#pragma unroll
            for (int tm = 0; tm < 2; tm++)
#pragma unroll
                for (int tn = 0; tn < 8; tn++) {
                    const uint32_t* bb = (tn & 1) ? &bfr[tn >> 1].z : &bfr[tn >> 1].x;
                    mma16(acc[tm][tn], afr[tm], bb);
                }
        }
    };

    load_stage(0, 0);
    load_stage(1, 1);
    cpa_wait<1>();
    __syncthreads();
#pragma unroll 1
    for (int it = 0; it < ITERS; ++it) {
        compute_stage(it & 1);
        __syncthreads();
        if (it + 2 < ITERS) {
            load_stage(it + 2, it & 1);
            cpa_wait<1>();
            __syncthreads();
        } else if (it + 1 < ITERS) {
            cpa_wait<0>();
            __syncthreads();
        }
    }

    // ---- epilogue ----
    if (MODE == 3) {
        // restage C (fp16) through smem, then emit GEMM2 B-fragment tiles directly
        __syncthreads();                       // all consumption of sA/sB done
        __half* sh = smem;                     // [128][136] halfs = 69632 B
#pragma unroll
        for (int tm = 0; tm < 2; tm++)
#pragma unroll
            for (int half = 0; half < 2; half++) {
                int r = wm + tm * 16 + (lane >> 2) + half * 8;
#pragma unroll
                for (int tn = 0; tn < 8; tn++) {
                    int c = wng * 64 + tn * 8 + (lane & 3) * 2;
                    __half2 h = __floats2half2_rn(acc[tm][tn][half * 2 + 0],
                                                  acc[tm][tn][half * 2 + 1]);
                    *(__half2*)(sh + r * 136 + c) = h;
                }
            }
        __syncthreads();
        const int slot = warp;
#pragma unroll
        for (int sub = 0; sub < 2; sub++) {     // two 64-row kt blocks
            int kt = blockIdx.x * 2 + sub;      // GEMM2 K-tile index (KT=16)
            __half* tile = g_MB + ((size_t)(e * 8 + blockIdx.y) * 16 + kt) * 8192;
#pragma unroll
            for (int j = 0; j < 4; j++) {
                int idx = slot * 4 + j;         // (ks, tp)
                int ks = idx >> 3, tp = idx & 7;
                int kb = sub * 64 + ks * 16 + 2 * (lane & 3);
                int n  = tp * 16 + (lane >> 2);
                __half h[8];
                h[0] = sh[kb * 136 + n];       h[1] = sh[(kb + 1) * 136 + n];
                h[2] = sh[(kb + 8) * 136 + n]; h[3] = sh[(kb + 9) * 136 + n];
                h[4] = sh[kb * 136 + n + 8];       h[5] = sh[(kb + 1) * 136 + n + 8];
                h[6] = sh[(kb + 8) * 136 + n + 8]; h[7] = sh[(kb + 9) * 136 + n + 8];
                *(uint4*)(tile + ks * 2048 + tp * 256 + lane * 8) = *(uint4*)h;
            }
        }
    } else {
#pragma unroll
        for (int tm = 0; tm < 2; tm++) {
#pragma unroll
            for (int half = 0; half < 2; half++) {
                int r  = wm + tm * 16 + (lane >> 2) + half * 8;
                int gr = m0 + r;
                if (gr < cnt) {
                    float w   = g_wsel[e * NUM_T + gr];
                    int   tok = g_list[e * NUM_T + gr];
                    float* orow = out + (size_t)tok * DIM + n0 + wng * 64;
#pragma unroll
                    for (int tn = 0; tn < 8; tn++) {
                        int c = tn * 8 + (lane & 3) * 2;
                        red2(orow + c,
                             w * acc[tm][tn][half * 2 + 0],
                             w * acc[tm][tn][half * 2 + 1]);
                    }
                }
            }
        }
    }
}

// ---------------- launch ----------------
extern "C" void kernel_launch(void* const* d_in, const int* in_sizes, int n_in,
                              void* d_out, int out_size) {
    const float* x  = (const float*)d_in[0];
    const float* wr = (const float*)d_in[1];
    const float* w1 = (const float*)d_in[2];
    const float* w2 = (const float*)d_in[3];
    float* out = (float*)d_out;

    cudaFuncSetAttribute(moe_gemm<DFFN, 3>,
                         cudaFuncAttributeMaxDynamicSharedMemorySize, SMEM_BYTES);
    cudaFuncSetAttribute(moe_gemm<DIM, 4>,
                         cudaFuncAttributeMaxDynamicSharedMemorySize, SMEM_BYTES);

    // launch order puts GEMM1 at position 5 (ncu -s 5 -c 1 captures it)
    cudaMemsetAsync(out, 0, (size_t)OUT_MAT * sizeof(float), 0);            // 1
    zero_kernel<<<1, 32>>>();                                               // 2
    convert_kernel<<<24576, 256>>>((const float4*)x, (const float4*)w1);    // 3
    frag_pack_w2<<<NEXP * 8 * (DFFN / 64), 256>>>(w2);                      // 4
    // GEMM1: M_e = W1_e @ W2_e, epilogue writes g_MB fragments directly    // 5
    moe_gemm<DFFN, 3><<<dim3(DIM / BM, DIM / BN, NEXP), 256, SMEM_BYTES>>>(nullptr);
    router_kernel<<<NUM_T / 16, 256>>>(x, wr);                              // 6
    finalize_kernel<<<1, 32>>>(out + OUT_MAT);                              // 7
    // GEMM2: out[tok] += wsel * (x_gathered @ M_e)                         // 8
    moe_gemm<DIM, 4><<<dim3(NUM_T / BM, DIM / BN, NEXP), 256, SMEM_BYTES>>>(out);
}